// round 7
// baseline (speedup 1.0000x reference)
#include <cuda_runtime.h>

#define NN 50000
#define EE 800000
#define INC 64
#define HID 128
#define NC1 64
#define NC2 16

#define NBP 296                 // pool blocks
#define PXS_DEN 12288           // 64*192
#define PXS_STRIDE 12292        // padded (x4B multiple of 16)
#define PAS_STRIDE 4096
#define RED_SIZE 16385

typedef unsigned long long u64;

// ---------------- scratch ----------------
__device__ __align__(256) float g_agg[NN * INC];
__device__ __align__(256) float g_x1[NN * HID];
__device__ __align__(256) float g_s[NN * NC1];
__device__ __align__(256) float g_As[NN * NC1];
__device__ __align__(256) float g_deg[NN];
__device__ __align__(256) float g_part_xs[NBP * PXS_STRIDE];
__device__ __align__(256) float g_part_as[NBP * PAS_STRIDE];
__device__ __align__(256) float g_red[16388];
__device__ __align__(256) float g_M[NC1 * NC1];
__device__ __align__(256) float g_s2[NC1 * NC2];

// ---------------- helpers ----------------
__device__ __forceinline__ void red_add_v4(float* p, float4 v) {
    asm volatile("red.global.add.v4.f32 [%0], {%1,%2,%3,%4};"
                 :: "l"(p), "f"(v.x), "f"(v.y), "f"(v.z), "f"(v.w) : "memory");
}
__device__ __forceinline__ void red_add_f32(float* p, float v) {
    asm volatile("red.global.add.f32 [%0], %1;" :: "l"(p), "f"(v) : "memory");
}
__device__ __forceinline__ u64 pack2(float x, float y) {
    u64 r; asm("mov.b64 %0, {%1, %2};" : "=l"(r) : "f"(x), "f"(y)); return r;
}
__device__ __forceinline__ void unpack2(float& x, float& y, u64 r) {
    asm("mov.b64 {%0, %1}, %2;" : "=f"(x), "=f"(y) : "l"(r));
}
__device__ __forceinline__ void fma2(u64& d, u64 a, u64 b) {
    asm("fma.rn.f32x2 %0, %1, %2, %0;" : "+l"(d) : "l"(a), "l"(b));
}

// ---------------- K0: zero ----------------
__global__ void k_zero() {
    int i = blockIdx.x * blockDim.x + threadIdx.x;
    float4 z = make_float4(0.f, 0.f, 0.f, 0.f);
    if (i < NN * INC / 4) ((float4*)g_agg)[i] = z;
    if (i < NN * NC1 / 4) ((float4*)g_As)[i] = z;
    if (i < NN / 4)       ((float4*)g_deg)[i] = z;
}

// ---------------- K1: agg[col] += mask[row]*x[row]; deg[row] += 1 ----------------
__global__ void k_scatter_agg(const float* __restrict__ x,
                              const int* __restrict__ row,
                              const int* __restrict__ col,
                              const float* __restrict__ mask) {
    int t = blockIdx.x * blockDim.x + threadIdx.x;
    int e = t >> 4, c4 = t & 15;
    int r = __ldg(row + e);
    if (c4 == 0) red_add_f32(g_deg + r, 1.0f);
    float m = __ldg(mask + r);
    if (m != 0.f) {
        int c = __ldg(col + e);
        float4 v = __ldg((const float4*)(x + (size_t)r * INC) + c4);
        red_add_v4(g_agg + (size_t)c * INC + c4 * 4, v);
    }
}

// ---------------- K2: fused GraphConv+ReLU, proj, LN, softmax/log_softmax
// Q=4 nodes/warp; all broadcast operands pre-DUPLICATED in smem -> fma2 reads
// natural 64-bit pairs, no pack2/MOV churn in the hot loops.
#define K2_Q 4
#define K2_THREADS 512
// floats: wrel 8192 | wroot 8192 | pw 8192 | biases 320 | insdup 16*Q*256 | x1dup 16*Q*256
#define K2_SMEM_FLOATS (8192*3 + 320 + 16*K2_Q*256*2)

__global__ __launch_bounds__(K2_THREADS, 1)
void k_node(const float* __restrict__ x, const float* __restrict__ mask,
            const float* __restrict__ W1rel, const float* __restrict__ b1,
            const float* __restrict__ W1root,
            const float* __restrict__ pW1, const float* __restrict__ pb1,
            const float* __restrict__ g1, const float* __restrict__ be1,
            float* __restrict__ out) {
    extern __shared__ float sm[];
    float* wrel  = sm;
    float* wroot = wrel + 8192;
    float* pwS   = wroot + 8192;
    float* b1s   = pwS + 8192;
    float* pb1s  = b1s + 128;
    float* g1s   = pb1s + 64;
    float* be1s  = g1s + 64;
    float* insdup = be1s + 64;                 // [16w][Q][256]: aggdup(128)|xddup(128)
    float* x1dup  = insdup + 16*K2_Q*256;      // [16w][Q][256]

    int tid = threadIdx.x;
    for (int i = tid; i < 8192; i += K2_THREADS) {
        int j = i >> 6, k = i & 63;            // W1* [128][64]
        wrel[k * 128 + j]  = W1rel[i];
        wroot[k * 128 + j] = W1root[i];
    }
    for (int i = tid; i < 8192; i += K2_THREADS) {
        int j = i >> 7, k = i & 127;           // pW1 [64][128]
        pwS[k * 64 + j] = pW1[i];
    }
    if (tid < 128) b1s[tid] = b1[tid];
    if (tid < 64) { pb1s[tid] = pb1[tid]; g1s[tid] = g1[tid]; be1s[tid] = be1[tid]; }
    __syncthreads();

    int w = tid >> 5, lane = tid & 31;
    int per = (NN + gridDim.x - 1) / gridDim.x;
    int n0 = blockIdx.x * per;
    int n1 = min(n0 + per, NN);
    float* insw = insdup + w * (K2_Q * 256);
    float* x1w  = x1dup  + w * (K2_Q * 256);

    float4 bv = ((float4*)b1s)[lane];
    u64 b_lo = pack2(bv.x, bv.y), b_hi = pack2(bv.z, bv.w);
    float2 pbv = ((float2*)pb1s)[lane];
    u64 pb_pk = pack2(pbv.x, pbv.y);
    float2 gg = ((float2*)g1s)[lane];
    float2 bb = ((float2*)be1s)[lane];

    for (int base = n0; base < n1; base += 16 * K2_Q) {
        int nb = base + w * K2_Q;
        // ---- stage Q nodes, duplicated: aggdup [0,128), xdrop dup [128,256) ----
        #pragma unroll
        for (int q = 0; q < K2_Q; q++) {
            int node = nb + q;
            int cn = node < NN ? node : NN - 1;
            float2* dst = (float2*)(insw + q * 256);
            if (lane < 16) {
                float4 v = *((const float4*)(g_agg + (size_t)cn * 64) + lane);
                dst[lane*4+0] = make_float2(v.x, v.x);
                dst[lane*4+1] = make_float2(v.y, v.y);
                dst[lane*4+2] = make_float2(v.z, v.z);
                dst[lane*4+3] = make_float2(v.w, v.w);
            } else {
                int k4 = lane - 16;
                float m = __ldg(mask + cn);
                float4 v = __ldg((const float4*)(x + (size_t)cn * 64) + k4);
                v.x *= m; v.y *= m; v.z *= m; v.w *= m;
                dst[64 + k4*4+0] = make_float2(v.x, v.x);
                dst[64 + k4*4+1] = make_float2(v.y, v.y);
                dst[64 + k4*4+2] = make_float2(v.z, v.z);
                dst[64 + k4*4+3] = make_float2(v.w, v.w);
            }
        }
        __syncwarp();

        // ---- GEMM1: x1[4*lane..+3] per node ----
        u64 acc_lo[K2_Q], acc_hi[K2_Q];
        #pragma unroll
        for (int q = 0; q < K2_Q; q++) { acc_lo[q] = b_lo; acc_hi[q] = b_hi; }
        #pragma unroll 16
        for (int k = 0; k < 64; k++) {
            ulonglong2 w1 = ((ulonglong2*)(wrel + k * 128))[lane];
            ulonglong2 w2 = ((ulonglong2*)(wroot + k * 128))[lane];
            #pragma unroll
            for (int q = 0; q < K2_Q; q++) {
                u64 ap = *(const u64*)(insw + q * 256 + 2 * k);
                u64 xp = *(const u64*)(insw + q * 256 + 128 + 2 * k);
                fma2(acc_lo[q], ap, w1.x);
                fma2(acc_hi[q], ap, w1.y);
                fma2(acc_lo[q], xp, w2.x);
                fma2(acc_hi[q], xp, w2.y);
            }
        }
        #pragma unroll
        for (int q = 0; q < K2_Q; q++) {
            float f0, f1, f2, f3;
            unpack2(f0, f1, acc_lo[q]);
            unpack2(f2, f3, acc_hi[q]);
            f0 = fmaxf(f0, 0.f); f1 = fmaxf(f1, 0.f);
            f2 = fmaxf(f2, 0.f); f3 = fmaxf(f3, 0.f);
            int node = nb + q;
            if (node < n1)
                *((float4*)(g_x1 + (size_t)node * 128) + lane) = make_float4(f0, f1, f2, f3);
            float2* xd = (float2*)(x1w + q * 256);
            xd[4*lane+0] = make_float2(f0, f0);
            xd[4*lane+1] = make_float2(f1, f1);
            xd[4*lane+2] = make_float2(f2, f2);
            xd[4*lane+3] = make_float2(f3, f3);
        }
        __syncwarp();

        // ---- proj: s1_raw[2*lane, 2*lane+1] ----
        u64 pacc[K2_Q];
        #pragma unroll
        for (int q = 0; q < K2_Q; q++) pacc[q] = pb_pk;
        #pragma unroll 16
        for (int k = 0; k < 128; k++) {
            u64 pw2 = ((const u64*)(pwS + k * 64))[lane];
            #pragma unroll
            for (int q = 0; q < K2_Q; q++) {
                u64 xp = *(const u64*)(x1w + q * 256 + 2 * k);
                fma2(pacc[q], xp, pw2);
            }
        }

        // ---- LN + softmax/log_softmax ----
        #pragma unroll
        for (int q = 0; q < K2_Q; q++) {
            int node = nb + q;
            float rx, ry;
            unpack2(rx, ry, pacc[q]);
            float sum = rx + ry, sq = rx * rx + ry * ry;
            #pragma unroll
            for (int o = 16; o; o >>= 1) {
                sum += __shfl_xor_sync(0xffffffffu, sum, o);
                sq  += __shfl_xor_sync(0xffffffffu, sq, o);
            }
            float mu  = sum * (1.f / 64.f);
            float var = sq * (1.f / 64.f) - mu * mu;
            float inv = rsqrtf(var + 1e-5f);
            float v0 = (rx - mu) * inv * gg.x + bb.x;
            float v1 = (ry - mu) * inv * gg.y + bb.y;
            float mx = fmaxf(v0, v1);
            #pragma unroll
            for (int o = 16; o; o >>= 1) mx = fmaxf(mx, __shfl_xor_sync(0xffffffffu, mx, o));
            float e0 = __expf(v0 - mx), e1 = __expf(v1 - mx);
            float se = e0 + e1;
            #pragma unroll
            for (int o = 16; o; o >>= 1) se += __shfl_xor_sync(0xffffffffu, se, o);
            float lse = __logf(se);
            float rinv = 1.f / se;
            if (node < n1) {
                ((float2*)(out + 4 + (size_t)node * 64))[lane] = make_float2(v0 - mx - lse, v1 - mx - lse);
                ((float2*)(g_s + (size_t)node * 64))[lane]     = make_float2(e0 * rinv, e1 * rinv);
            }
        }
        __syncwarp();
    }
}

// ---------------- K_mid: pool_xs blocks (0..NBP) || scatter_As blocks ----------------
// pool_xs: s^T @ [x1 | s] (64x192) + mincut denominator
// scatter: A_s[row[e]] += s[col[e]]  (L2-atomic bound, runs concurrently)
__global__ void k_mid(const int* __restrict__ row, const int* __restrict__ col) {
    if (blockIdx.x < NBP) {
        __shared__ __align__(16) float vv[2][4][192];
        __shared__ float redsh[256];
        int t = threadIdx.x;
        int rg = t >> 4, cg = t & 15;
        int per = (NN + NBP - 1) / NBP;
        int n0 = blockIdx.x * per;
        int n1 = min(n0 + per, NN);

        const float* src;
        int stride;
        if (t < 128)      { src = g_x1 + t;         stride = 128; }
        else if (t < 192) { src = g_s + (t - 128);  stride = 64; }
        else              { src = g_s + (t - 192);  stride = 64; }

        u64 acc[4][6];
        #pragma unroll
        for (int i = 0; i < 4; i++)
            #pragma unroll
            for (int j = 0; j < 6; j++) acc[i][j] = 0ULL;
        float denp = 0.f;

        float r[4], dg[4];
        #pragma unroll
        for (int j = 0; j < 4; j++) {
            int n = n0 + j;
            r[j]  = (n < n1) ? src[(size_t)n * stride] : 0.f;
            dg[j] = (t >= 192 && n < n1) ? __ldg(g_deg + n) : 0.f;
        }
        int pi = 0;
        for (int g = n0; g < n1; g += 4) {
            if (t < 192) {
                #pragma unroll
                for (int j = 0; j < 4; j++) vv[pi][j][t] = r[j];
            } else {
                #pragma unroll
                for (int j = 0; j < 4; j++) denp += dg[j] * r[j] * r[j];
            }
            float rn[4], dn[4];
            #pragma unroll
            for (int j = 0; j < 4; j++) {
                int n = g + 4 + j;
                rn[j] = (n < n1) ? src[(size_t)n * stride] : 0.f;
                dn[j] = (t >= 192 && n < n1) ? __ldg(g_deg + n) : 0.f;
            }
            __syncthreads();
            #pragma unroll
            for (int j = 0; j < 4; j++) {
                float4 s4 = *(const float4*)&vv[pi][j][128 + rg * 4];
                u64 s0 = pack2(s4.x, s4.x), s1 = pack2(s4.y, s4.y);
                u64 s2 = pack2(s4.z, s4.z), s3 = pack2(s4.w, s4.w);
                const ulonglong2* vp = (const ulonglong2*)&vv[pi][j][cg * 12];
                #pragma unroll
                for (int h = 0; h < 3; h++) {
                    ulonglong2 b2v = vp[h];
                    fma2(acc[0][2*h], s0, b2v.x); fma2(acc[0][2*h+1], s0, b2v.y);
                    fma2(acc[1][2*h], s1, b2v.x); fma2(acc[1][2*h+1], s1, b2v.y);
                    fma2(acc[2][2*h], s2, b2v.x); fma2(acc[2][2*h+1], s2, b2v.y);
                    fma2(acc[3][2*h], s3, b2v.x); fma2(acc[3][2*h+1], s3, b2v.y);
                }
            }
            pi ^= 1;
            #pragma unroll
            for (int j = 0; j < 4; j++) { r[j] = rn[j]; dg[j] = dn[j]; }
        }
        float* base = g_part_xs + (size_t)blockIdx.x * PXS_STRIDE;
        #pragma unroll
        for (int i = 0; i < 4; i++)
            #pragma unroll
            for (int j = 0; j < 6; j++) {
                float f0, f1;
                unpack2(f0, f1, acc[i][j]);
                ((float2*)(base + (rg * 4 + i) * 192 + cg * 12))[j] = make_float2(f0, f1);
            }
        redsh[t] = denp; __syncthreads();
        for (int o = 128; o; o >>= 1) { if (t < o) redsh[t] += redsh[t + o]; __syncthreads(); }
        if (t == 0) base[PXS_DEN] = redsh[0];
    } else {
        int task = (blockIdx.x - NBP) * 256 + threadIdx.x;   // EE*16 tasks exactly
        int e = task >> 4, c4 = task & 15;
        int r = __ldg(row + e);
        int c = __ldg(col + e);
        float4 v = __ldg((const float4*)(g_s + (size_t)c * NC1) + c4);
        red_add_v4(g_As + (size_t)r * NC1 + c4 * 4, v);
    }
}

// ---------------- K_pool_as: s^T @ A_s (64x64) ----------------
__global__ void k_pool_as() {
    __shared__ __align__(16) float sAs[2][4][64];
    __shared__ __align__(16) float sS[2][4][64];
    int t = threadIdx.x;
    int rg = t >> 4, cg = t & 15;
    int j0 = t >> 6, u = t & 63;
    int per = (NN + NBP - 1) / NBP;
    int n0 = blockIdx.x * per;
    int n1 = min(n0 + per, NN);

    u64 acc[4][2];
    #pragma unroll
    for (int i = 0; i < 4; i++) { acc[i][0] = 0ULL; acc[i][1] = 0ULL; }

    float ra, rs;
    {
        int n = n0 + j0;
        ra = (n < n1) ? g_As[(size_t)n * 64 + u] : 0.f;
        rs = (n < n1) ? g_s[(size_t)n * 64 + u]  : 0.f;
    }
    int pi = 0;
    for (int g = n0; g < n1; g += 4) {
        sAs[pi][j0][u] = ra;
        sS[pi][j0][u]  = rs;
        float ran, rsn;
        {
            int n = g + 4 + j0;
            ran = (n < n1) ? g_As[(size_t)n * 64 + u] : 0.f;
            rsn = (n < n1) ? g_s[(size_t)n * 64 + u]  : 0.f;
        }
        __syncthreads();
        #pragma unroll
        for (int j = 0; j < 4; j++) {
            float4 s4 = *(const float4*)&sS[pi][j][rg * 4];
            u64 s0 = pack2(s4.x, s4.x), s1 = pack2(s4.y, s4.y);
            u64 s2 = pack2(s4.z, s4.z), s3 = pack2(s4.w, s4.w);
            ulonglong2 b2v = *(const ulonglong2*)&sAs[pi][j][cg * 4];
            fma2(acc[0][0], s0, b2v.x); fma2(acc[0][1], s0, b2v.y);
            fma2(acc[1][0], s1, b2v.x); fma2(acc[1][1], s1, b2v.y);
            fma2(acc[2][0], s2, b2v.x); fma2(acc[2][1], s2, b2v.y);
            fma2(acc[3][0], s3, b2v.x); fma2(acc[3][1], s3, b2v.y);
        }
        pi ^= 1;
        ra = ran; rs = rsn;
    }
    float* base = g_part_as + (size_t)blockIdx.x * PAS_STRIDE;
    #pragma unroll
    for (int i = 0; i < 4; i++) {
        float f0, f1;
        unpack2(f0, f1, acc[i][0]);
        ((float2*)(base + (rg * 4 + i) * 64 + cg * 4))[0] = make_float2(f0, f1);
        unpack2(f0, f1, acc[i][1]);
        ((float2*)(base + (rg * 4 + i) * 64 + cg * 4))[1] = make_float2(f0, f1);
    }
}

// ---------------- K_reduce: merge partials into g_red [64][256] + den ----------------
__global__ void k_reduce() {
    int i = blockIdx.x * blockDim.x + threadIdx.x;
    if (i >= RED_SIZE) return;
    float s = 0.f;
    if (i == 16384) {
        for (int b = 0; b < NBP; b++) s += g_part_xs[(size_t)b * PXS_STRIDE + PXS_DEN];
    } else {
        int a = i >> 8, c = i & 255;
        if (c < 128) {
            int off = a * 192 + c;
            for (int b = 0; b < NBP; b++) s += g_part_xs[(size_t)b * PXS_STRIDE + off];
        } else if (c < 192) {
            int off = a * 64 + (c - 128);
            for (int b = 0; b < NBP; b++) s += g_part_as[(size_t)b * PAS_STRIDE + off];
        } else {
            int off = a * 192 + 128 + (c - 192);
            for (int b = 0; b < NBP; b++) s += g_part_xs[(size_t)b * PXS_STRIDE + off];
        }
    }
    g_red[i] = s;
}

// ---------------- K4m: mc1, o1, pruning -> M ----------------
__global__ void k_small1(float* __restrict__ out) {
    __shared__ float sadj[64 * 65];
    __shared__ float ssts[64 * 65];
    __shared__ float red[256];
    __shared__ float dsi[64];
    int t = threadIdx.x;
    for (int i = t; i < 4096; i += 256) {
        int c = i >> 6, j = i & 63;
        sadj[c * 65 + j] = g_red[c * 256 + 128 + j];
        ssts[c * 65 + j] = g_red[c * 256 + 192 + j];
    }
    __syncthreads();
    float p = 0.f;
    #pragma unroll 4
    for (int i = t; i < 4096; i += 256) {
        float v = ssts[(i >> 6) * 65 + (i & 63)];
        p += v * v;
    }
    red[t] = p; __syncthreads();
    for (int o = 128; o; o >>= 1) { if (t < o) red[t] += red[t + o]; __syncthreads(); }
    float nrm = sqrtf(red[0]); __syncthreads();
    float q = 0.f;
    #pragma unroll 4
    for (int i = t; i < 4096; i += 256) {
        int c = i >> 6, j = i & 63;
        float v = ssts[c * 65 + j] / (nrm + 1e-10f) - ((c == j) ? 0.125f : 0.f);
        q += v * v;
    }
    red[t] = q; __syncthreads();
    for (int o = 128; o; o >>= 1) { if (t < o) red[t] += red[t + o]; __syncthreads(); }
    float o1 = sqrtf(red[0]); __syncthreads();
    float tp = (t < 64) ? sadj[t * 65 + t] : 0.f;
    red[t] = tp; __syncthreads();
    for (int o = 128; o; o >>= 1) { if (t < o) red[t] += red[t + o]; __syncthreads(); }
    if (t == 0) {
        float den = g_red[16384];
        out[0] = -red[0] / (den + 1e-10f);
        out[1] = o1;
    }
    __syncthreads();
    if (t < 64) {
        float rs = 0.f;
        #pragma unroll
        for (int j = 0; j < 64; j++) if (j != t) rs += sadj[t * 65 + j];
        dsi[t] = 1.f / (sqrtf(rs) + 1e-15f);
    }
    __syncthreads();
    for (int i = t; i < 4096; i += 256) {
        int c = i >> 6, j = i & 63;
        float a = (c == j) ? 0.f : (sadj[c * 65 + j] * dsi[c] * dsi[j]);
        g_M[i] = (a > (1.0f / 63.0f)) ? 1.f : 0.f;
    }
}

// ---------------- K4a: pooled GraphConv + LN + softmax ----------------
#define L2_SMEM_FLOATS (16512*2 + 2048 + 128*4 + 16*2 + 64)

__global__ void k_layer2(const float* __restrict__ W2rel, const float* __restrict__ b2,
                         const float* __restrict__ W2root,
                         const float* __restrict__ pW2, const float* __restrict__ pb2,
                         const float* __restrict__ g2, const float* __restrict__ be2,
                         float* __restrict__ out) {
    extern __shared__ float sm2[];
    float* w2a  = sm2;
    float* w2b  = w2a + 16512;
    float* pws  = w2b + 16512;
    float* ag   = pws + 2048;
    float* pr   = ag + 128;
    float* x2r  = pr + 128;
    float* praw = x2r + 128;
    float* r16  = praw + 128;
    float* v16  = r16 + 16;
    float* Mcol = v16 + 16;
    int c = blockIdx.x;
    int t = threadIdx.x;

    for (int i = t; i < 16384; i += 128) {
        int o = i >> 7, k = i & 127;
        w2a[k * 129 + o] = W2rel[i];
        w2b[k * 129 + o] = W2root[i];
    }
    for (int i = t; i < 2048; i += 128) pws[i] = pW2[i];
    if (t < 64) Mcol[t] = g_M[t * 64 + c];
    pr[t] = g_red[c * 256 + t];
    __syncthreads();

    float a = 0.f;
    #pragma unroll 16
    for (int cp = 0; cp < 64; cp++) a += Mcol[cp] * g_red[cp * 256 + t];
    ag[t] = a;
    __syncthreads();

    float acc = __ldg(b2 + t);
    #pragma unroll 8
    for (int k = 0; k < 128; k++)
        acc += ag[k] * w2a[k * 129 + t] + pr[k] * w2b[k * 129 + t];
    acc = fmaxf(acc, 0.f);
    x2r[t] = acc;
    __syncthreads();
    {
        int j2 = t >> 3, seg = t & 7;
        float p = 0.f;
        #pragma unroll
        for (int k = seg; k < 128; k += 8) p += x2r[k] * pws[j2 * 128 + k];
        praw[t] = p;
    }
    __syncthreads();
    if (t < 16) {
        float raw = pb2[t];
        #pragma unroll
        for (int s = 0; s < 8; s++) raw += praw[t * 8 + s];
        r16[t] = raw;
    }
    __syncthreads();
    if (t < 16) {
        float mu = 0.f, sq = 0.f;
        #pragma unroll
        for (int j = 0; j < 16; j++) { mu += r16[j]; sq += r16[j] * r16[j]; }
        mu *= (1.f / 16.f);
        float var = sq * (1.f / 16.f) - mu * mu;
        v16[t] = (r16[t] - mu) * rsqrtf(var + 1e-5f) * g2[t] + be2[t];
    }
    __syncthreads();
    if (t < 16) {
        float mx = -1e30f;
        #pragma unroll
        for (int j = 0; j < 16; j++) mx = fmaxf(mx, v16[j]);
        float se = 0.f;
        #pragma unroll
        for (int j = 0; j < 16; j++) se += __expf(v16[j] - mx);
        float e = __expf(v16[t] - mx);
        out[4 + NN * 64 + c * 16 + t] = v16[t] - mx - __logf(se);
        g_s2[c * 16 + t] = e / se;
    }
}

// ---------------- K4b: dense mincut -> mc2, o2 ----------------
__global__ void k_small2(float* __restrict__ out) {
    __shared__ float sM[64 * 65];
    __shared__ float s2s[NC1 * NC2];
    __shared__ float As2[NC1 * NC2];
    __shared__ float padj[NC2 * NC2];
    __shared__ float sTs[NC2 * NC2];
    __shared__ float red[256];
    int t = threadIdx.x;
    for (int i = t; i < 4096; i += 256) sM[(i >> 6) * 65 + (i & 63)] = g_M[i];
    for (int i = t; i < 1024; i += 256) s2s[i] = g_s2[i];
    __syncthreads();
    for (int i = t; i < 1024; i += 256) {
        int c = i >> 4, j = i & 15;
        float a = 0.f;
        #pragma unroll 16
        for (int cp = 0; cp < 64; cp++) a += sM[c * 65 + cp] * s2s[cp * 16 + j];
        As2[i] = a;
    }
    __syncthreads();
    {
        int aI = t >> 4, bI = t & 15;
        float pa = 0.f, st = 0.f;
        #pragma unroll 16
        for (int c = 0; c < 64; c++) {
            float sa = s2s[c * 16 + aI];
            pa += sa * As2[c * 16 + bI];
            st += sa * s2s[c * 16 + bI];
        }
        padj[t] = pa; sTs[t] = st;
    }
    __syncthreads();
    float dp = 0.f;
    if (t < 64) {
        float d = 0.f;
        #pragma unroll
        for (int j = 0; j < 64; j++) d += sM[t * 65 + j];
        float accv = 0.f;
        #pragma unroll
        for (int j = 0; j < 16; j++) { float s = s2s[t * 16 + j]; accv += s * s; }
        dp = d * accv;
    }
    red[t] = dp; __syncthreads();
    for (int o = 128; o; o >>= 1) { if (t < o) red[t] += red[t + o]; __syncthreads(); }
    float den2 = red[0]; __syncthreads();
    float trp = (t < 16) ? padj[t * 16 + t] : 0.f;
    red[t] = trp; __syncthreads();
    for (int o = 128; o; o >>= 1) { if (t < o) red[t] += red[t + o]; __syncthreads(); }
    float tr2 = red[0]; __syncthreads();
    float np = sTs[t] * sTs[t];
    red[t] = np; __syncthreads();
    for (int o = 128; o; o >>= 1) { if (t < o) red[t] += red[t + o]; __syncthreads(); }
    float norm2 = sqrtf(red[0]); __syncthreads();
    float diff = sTs[t] / (norm2 + 1e-10f) - (((t >> 4) == (t & 15)) ? 0.25f : 0.f);
    red[t] = diff * diff; __syncthreads();
    for (int o = 128; o; o >>= 1) { if (t < o) red[t] += red[t + o]; __syncthreads(); }
    if (t == 0) {
        out[2] = -tr2 / (den2 + 1e-10f);
        out[3] = sqrtf(red[0]);
    }
}

// ---------------- launch ----------------
extern "C" void kernel_launch(void* const* d_in, const int* in_sizes, int n_in,
                              void* d_out, int out_size) {
    const float* x     = (const float*)d_in[0];
    const int*   ei    = (const int*)d_in[1];
    const float* mask  = (const float*)d_in[2];
    const float* W1rel = (const float*)d_in[3];
    const float* b1    = (const float*)d_in[4];
    const float* W1rt  = (const float*)d_in[5];
    const float* pW1   = (const float*)d_in[6];
    const float* pb1   = (const float*)d_in[7];
    const float* g1    = (const float*)d_in[8];
    const float* be1   = (const float*)d_in[9];
    const float* W2rel = (const float*)d_in[10];
    const float* b2    = (const float*)d_in[11];
    const float* W2rt  = (const float*)d_in[12];
    const float* pW2   = (const float*)d_in[13];
    const float* pb2   = (const float*)d_in[14];
    const float* g2    = (const float*)d_in[15];
    const float* be2   = (const float*)d_in[16];
    float* out = (float*)d_out;
    const int* row = ei;
    const int* col = ei + EE;

    cudaFuncSetAttribute(k_node, cudaFuncAttributeMaxDynamicSharedMemorySize,
                         K2_SMEM_FLOATS * (int)sizeof(float));
    cudaFuncSetAttribute(k_layer2, cudaFuncAttributeMaxDynamicSharedMemorySize,
                         L2_SMEM_FLOATS * (int)sizeof(float));

    k_zero<<<(NN * INC / 4 + 255) / 256, 256>>>();
    k_scatter_agg<<<(EE * 16) / 256, 256>>>(x, row, col, mask);
    k_node<<<148, K2_THREADS, K2_SMEM_FLOATS * sizeof(float)>>>(
        x, mask, W1rel, b1, W1rt, pW1, pb1, g1, be1, out);
    k_mid<<<NBP + (EE * 16) / 256, 256>>>(row, col);   // pool_xs || scatter_As
    k_pool_as<<<NBP, 256>>>();
    k_reduce<<<(RED_SIZE + 255) / 256, 256>>>();
    k_small1<<<1, 256>>>(out);
    k_layer2<<<64, 128, L2_SMEM_FLOATS * sizeof(float)>>>(W2rel, b2, W2rt, pW2, pb2, g2, be2, out);
    k_small2<<<1, 256>>>(out);
}

// round 10
// speedup vs baseline: 1.2716x; 1.2716x over previous
#include <cuda_runtime.h>

#define NN 50000
#define EE 800000
#define INC 64
#define HID 128
#define NC1 64
#define NC2 16

#define NBP 296                 // pool blocks
#define PXS_DEN 12288           // 64*192
#define PXS_STRIDE 12292        // padded
#define PAS_STRIDE 4096
#define RED_SIZE 16385

typedef unsigned long long u64;

// ---------------- scratch ----------------
__device__ __align__(256) float g_agg[NN * INC];
__device__ __align__(256) float g_x1[NN * HID];
__device__ __align__(256) float g_s[NN * NC1];
__device__ __align__(256) float g_As[NN * NC1];
__device__ __align__(256) float g_deg[NN];
__device__ __align__(256) float g_part_xs[NBP * PXS_STRIDE];
__device__ __align__(256) float g_part_as[NBP * PAS_STRIDE];
__device__ __align__(256) float g_red[16388];
__device__ __align__(256) float g_M[NC1 * NC1];
__device__ __align__(256) float g_s2[NC1 * NC2];

// ---------------- helpers ----------------
__device__ __forceinline__ void red_add_v4(float* p, float4 v) {
    asm volatile("red.global.add.v4.f32 [%0], {%1,%2,%3,%4};"
                 :: "l"(p), "f"(v.x), "f"(v.y), "f"(v.z), "f"(v.w) : "memory");
}
__device__ __forceinline__ void red_add_f32(float* p, float v) {
    asm volatile("red.global.add.f32 [%0], %1;" :: "l"(p), "f"(v) : "memory");
}
__device__ __forceinline__ u64 pack2(float x, float y) {
    u64 r; asm("mov.b64 %0, {%1, %2};" : "=l"(r) : "f"(x), "f"(y)); return r;
}
__device__ __forceinline__ void unpack2(float& x, float& y, u64 r) {
    asm("mov.b64 {%0, %1}, %2;" : "=f"(x), "=f"(y) : "l"(r));
}
__device__ __forceinline__ void fma2(u64& d, u64 a, u64 b) {
    asm("fma.rn.f32x2 %0, %1, %2, %0;" : "+l"(d) : "l"(a), "l"(b));
}

// ---------------- K0: zero ----------------
__global__ void k_zero() {
    int i = blockIdx.x * blockDim.x + threadIdx.x;
    float4 z = make_float4(0.f, 0.f, 0.f, 0.f);
    if (i < NN * INC / 4) ((float4*)g_agg)[i] = z;
    if (i < NN * NC1 / 4) ((float4*)g_As)[i] = z;
    if (i < NN / 4)       ((float4*)g_deg)[i] = z;
}

// ---------------- K1: agg[col] += mask[row]*x[row]; deg[row] += 1 ----------------
__global__ void k_scatter_agg(const float* __restrict__ x,
                              const int* __restrict__ row,
                              const int* __restrict__ col,
                              const float* __restrict__ mask) {
    int t = blockIdx.x * blockDim.x + threadIdx.x;
    int e = t >> 4, c4 = t & 15;
    int r = __ldg(row + e);
    if (c4 == 0) red_add_f32(g_deg + r, 1.0f);
    float m = __ldg(mask + r);
    if (m != 0.f) {
        int c = __ldg(col + e);
        float4 v = __ldg((const float4*)(x + (size_t)r * INC) + c4);
        red_add_v4(g_agg + (size_t)c * INC + c4 * 4, v);
    }
}

// ---------------- K1b: A_s[row[e]] += s[col[e]]  (standalone: 16 regs, high occ) ----
__global__ void k_scatter_As(const int* __restrict__ row,
                             const int* __restrict__ col) {
    int t = blockIdx.x * blockDim.x + threadIdx.x;
    int e = t >> 4, c4 = t & 15;
    int r = __ldg(row + e);
    int c = __ldg(col + e);
    float4 v = __ldg((const float4*)(g_s + (size_t)c * NC1) + c4);
    red_add_v4(g_As + (size_t)r * NC1 + c4 * 4, v);
}

// ---------------- K2: fused GraphConv+ReLU, proj, LN, softmax/log_softmax
// Q=4 nodes/warp; broadcast operands pre-DUPLICATED in smem -> fma2 reads
// natural 64-bit pairs.
#define K2_Q 4
#define K2_THREADS 512
#define K2_SMEM_FLOATS (8192*3 + 320 + 16*K2_Q*256*2)

__global__ __launch_bounds__(K2_THREADS, 1)
void k_node(const float* __restrict__ x, const float* __restrict__ mask,
            const float* __restrict__ W1rel, const float* __restrict__ b1,
            const float* __restrict__ W1root,
            const float* __restrict__ pW1, const float* __restrict__ pb1,
            const float* __restrict__ g1, const float* __restrict__ be1,
            float* __restrict__ out) {
    extern __shared__ float sm[];
    float* wrel  = sm;
    float* wroot = wrel + 8192;
    float* pwS   = wroot + 8192;
    float* b1s   = pwS + 8192;
    float* pb1s  = b1s + 128;
    float* g1s   = pb1s + 64;
    float* be1s  = g1s + 64;
    float* insdup = be1s + 64;                 // [16w][Q][256]
    float* x1dup  = insdup + 16*K2_Q*256;      // [16w][Q][256]

    int tid = threadIdx.x;
    for (int i = tid; i < 8192; i += K2_THREADS) {
        int j = i >> 6, k = i & 63;
        wrel[k * 128 + j]  = W1rel[i];
        wroot[k * 128 + j] = W1root[i];
    }
    for (int i = tid; i < 8192; i += K2_THREADS) {
        int j = i >> 7, k = i & 127;
        pwS[k * 64 + j] = pW1[i];
    }
    if (tid < 128) b1s[tid] = b1[tid];
    if (tid < 64) { pb1s[tid] = pb1[tid]; g1s[tid] = g1[tid]; be1s[tid] = be1[tid]; }
    __syncthreads();

    int w = tid >> 5, lane = tid & 31;
    int per = (NN + gridDim.x - 1) / gridDim.x;
    int n0 = blockIdx.x * per;
    int n1 = min(n0 + per, NN);
    float* insw = insdup + w * (K2_Q * 256);
    float* x1w  = x1dup  + w * (K2_Q * 256);

    float4 bv = ((float4*)b1s)[lane];
    u64 b_lo = pack2(bv.x, bv.y), b_hi = pack2(bv.z, bv.w);
    float2 pbv = ((float2*)pb1s)[lane];
    u64 pb_pk = pack2(pbv.x, pbv.y);
    float2 gg = ((float2*)g1s)[lane];
    float2 bb = ((float2*)be1s)[lane];

    for (int base = n0; base < n1; base += 16 * K2_Q) {
        int nb = base + w * K2_Q;
        #pragma unroll
        for (int q = 0; q < K2_Q; q++) {
            int node = nb + q;
            int cn = node < NN ? node : NN - 1;
            float2* dst = (float2*)(insw + q * 256);
            if (lane < 16) {
                float4 v = *((const float4*)(g_agg + (size_t)cn * 64) + lane);
                dst[lane*4+0] = make_float2(v.x, v.x);
                dst[lane*4+1] = make_float2(v.y, v.y);
                dst[lane*4+2] = make_float2(v.z, v.z);
                dst[lane*4+3] = make_float2(v.w, v.w);
            } else {
                int k4 = lane - 16;
                float m = __ldg(mask + cn);
                float4 v = __ldg((const float4*)(x + (size_t)cn * 64) + k4);
                v.x *= m; v.y *= m; v.z *= m; v.w *= m;
                dst[64 + k4*4+0] = make_float2(v.x, v.x);
                dst[64 + k4*4+1] = make_float2(v.y, v.y);
                dst[64 + k4*4+2] = make_float2(v.z, v.z);
                dst[64 + k4*4+3] = make_float2(v.w, v.w);
            }
        }
        __syncwarp();

        u64 acc_lo[K2_Q], acc_hi[K2_Q];
        #pragma unroll
        for (int q = 0; q < K2_Q; q++) { acc_lo[q] = b_lo; acc_hi[q] = b_hi; }
        #pragma unroll 16
        for (int k = 0; k < 64; k++) {
            ulonglong2 w1 = ((ulonglong2*)(wrel + k * 128))[lane];
            ulonglong2 w2 = ((ulonglong2*)(wroot + k * 128))[lane];
            #pragma unroll
            for (int q = 0; q < K2_Q; q++) {
                u64 ap = *(const u64*)(insw + q * 256 + 2 * k);
                u64 xp = *(const u64*)(insw + q * 256 + 128 + 2 * k);
                fma2(acc_lo[q], ap, w1.x);
                fma2(acc_hi[q], ap, w1.y);
                fma2(acc_lo[q], xp, w2.x);
                fma2(acc_hi[q], xp, w2.y);
            }
        }
        #pragma unroll
        for (int q = 0; q < K2_Q; q++) {
            float f0, f1, f2, f3;
            unpack2(f0, f1, acc_lo[q]);
            unpack2(f2, f3, acc_hi[q]);
            f0 = fmaxf(f0, 0.f); f1 = fmaxf(f1, 0.f);
            f2 = fmaxf(f2, 0.f); f3 = fmaxf(f3, 0.f);
            int node = nb + q;
            if (node < n1)
                *((float4*)(g_x1 + (size_t)node * 128) + lane) = make_float4(f0, f1, f2, f3);
            float2* xd = (float2*)(x1w + q * 256);
            xd[4*lane+0] = make_float2(f0, f0);
            xd[4*lane+1] = make_float2(f1, f1);
            xd[4*lane+2] = make_float2(f2, f2);
            xd[4*lane+3] = make_float2(f3, f3);
        }
        __syncwarp();

        u64 pacc[K2_Q];
        #pragma unroll
        for (int q = 0; q < K2_Q; q++) pacc[q] = pb_pk;
        #pragma unroll 16
        for (int k = 0; k < 128; k++) {
            u64 pw2 = ((const u64*)(pwS + k * 64))[lane];
            #pragma unroll
            for (int q = 0; q < K2_Q; q++) {
                u64 xp = *(const u64*)(x1w + q * 256 + 2 * k);
                fma2(pacc[q], xp, pw2);
            }
        }

        #pragma unroll
        for (int q = 0; q < K2_Q; q++) {
            int node = nb + q;
            float rx, ry;
            unpack2(rx, ry, pacc[q]);
            float sum = rx + ry, sq = rx * rx + ry * ry;
            #pragma unroll
            for (int o = 16; o; o >>= 1) {
                sum += __shfl_xor_sync(0xffffffffu, sum, o);
                sq  += __shfl_xor_sync(0xffffffffu, sq, o);
            }
            float mu  = sum * (1.f / 64.f);
            float var = sq * (1.f / 64.f) - mu * mu;
            float inv = rsqrtf(var + 1e-5f);
            float v0 = (rx - mu) * inv * gg.x + bb.x;
            float v1 = (ry - mu) * inv * gg.y + bb.y;
            float mx = fmaxf(v0, v1);
            #pragma unroll
            for (int o = 16; o; o >>= 1) mx = fmaxf(mx, __shfl_xor_sync(0xffffffffu, mx, o));
            float e0 = __expf(v0 - mx), e1 = __expf(v1 - mx);
            float se = e0 + e1;
            #pragma unroll
            for (int o = 16; o; o >>= 1) se += __shfl_xor_sync(0xffffffffu, se, o);
            float lse = __logf(se);
            float rinv = 1.f / se;
            if (node < n1) {
                ((float2*)(out + 4 + (size_t)node * 64))[lane] = make_float2(v0 - mx - lse, v1 - mx - lse);
                ((float2*)(g_s + (size_t)node * 64))[lane]     = make_float2(e0 * rinv, e1 * rinv);
            }
        }
        __syncwarp();
    }
}

// ---------------- K_pool_xs: s^T @ [x1 | s] (64x192) + mincut denominator -------
__global__ void k_pool_xs() {
    __shared__ __align__(16) float vv[2][4][192];
    __shared__ float redsh[256];
    int t = threadIdx.x;
    int rg = t >> 4, cg = t & 15;
    int per = (NN + NBP - 1) / NBP;
    int n0 = blockIdx.x * per;
    int n1 = min(n0 + per, NN);

    const float* src;
    int stride;
    if (t < 128)      { src = g_x1 + t;         stride = 128; }
    else if (t < 192) { src = g_s + (t - 128);  stride = 64; }
    else              { src = g_s + (t - 192);  stride = 64; }

    u64 acc[4][6];
    #pragma unroll
    for (int i = 0; i < 4; i++)
        #pragma unroll
        for (int j = 0; j < 6; j++) acc[i][j] = 0ULL;
    float denp = 0.f;

    float r[4], dg[4];
    #pragma unroll
    for (int j = 0; j < 4; j++) {
        int n = n0 + j;
        r[j]  = (n < n1) ? src[(size_t)n * stride] : 0.f;
        dg[j] = (t >= 192 && n < n1) ? __ldg(g_deg + n) : 0.f;
    }
    int pi = 0;
    for (int g = n0; g < n1; g += 4) {
        if (t < 192) {
            #pragma unroll
            for (int j = 0; j < 4; j++) vv[pi][j][t] = r[j];
        } else {
            #pragma unroll
            for (int j = 0; j < 4; j++) denp += dg[j] * r[j] * r[j];
        }
        float rn[4], dn[4];
        #pragma unroll
        for (int j = 0; j < 4; j++) {
            int n = g + 4 + j;
            rn[j] = (n < n1) ? src[(size_t)n * stride] : 0.f;
            dn[j] = (t >= 192 && n < n1) ? __ldg(g_deg + n) : 0.f;
        }
        __syncthreads();
        #pragma unroll
        for (int j = 0; j < 4; j++) {
            float4 s4 = *(const float4*)&vv[pi][j][128 + rg * 4];
            u64 s0 = pack2(s4.x, s4.x), s1 = pack2(s4.y, s4.y);
            u64 s2 = pack2(s4.z, s4.z), s3 = pack2(s4.w, s4.w);
            const ulonglong2* vp = (const ulonglong2*)&vv[pi][j][cg * 12];
            #pragma unroll
            for (int h = 0; h < 3; h++) {
                ulonglong2 b2v = vp[h];
                fma2(acc[0][2*h], s0, b2v.x); fma2(acc[0][2*h+1], s0, b2v.y);
                fma2(acc[1][2*h], s1, b2v.x); fma2(acc[1][2*h+1], s1, b2v.y);
                fma2(acc[2][2*h], s2, b2v.x); fma2(acc[2][2*h+1], s2, b2v.y);
                fma2(acc[3][2*h], s3, b2v.x); fma2(acc[3][2*h+1], s3, b2v.y);
            }
        }
        pi ^= 1;
        #pragma unroll
        for (int j = 0; j < 4; j++) { r[j] = rn[j]; dg[j] = dn[j]; }
    }
    float* base = g_part_xs + (size_t)blockIdx.x * PXS_STRIDE;
    #pragma unroll
    for (int i = 0; i < 4; i++)
        #pragma unroll
        for (int j = 0; j < 6; j++) {
            float f0, f1;
            unpack2(f0, f1, acc[i][j]);
            ((float2*)(base + (rg * 4 + i) * 192 + cg * 12))[j] = make_float2(f0, f1);
        }
    redsh[t] = denp; __syncthreads();
    for (int o = 128; o; o >>= 1) { if (t < o) redsh[t] += redsh[t + o]; __syncthreads(); }
    if (t == 0) base[PXS_DEN] = redsh[0];
}

// ---------------- K_pool_as: s^T @ A_s (64x64) ----------------
__global__ void k_pool_as() {
    __shared__ __align__(16) float sAs[2][4][64];
    __shared__ __align__(16) float sS[2][4][64];
    int t = threadIdx.x;
    int rg = t >> 4, cg = t & 15;
    int j0 = t >> 6, u = t & 63;
    int per = (NN + NBP - 1) / NBP;
    int n0 = blockIdx.x * per;
    int n1 = min(n0 + per, NN);

    u64 acc[4][2];
    #pragma unroll
    for (int i = 0; i < 4; i++) { acc[i][0] = 0ULL; acc[i][1] = 0ULL; }

    float ra, rs;
    {
        int n = n0 + j0;
        ra = (n < n1) ? g_As[(size_t)n * 64 + u] : 0.f;
        rs = (n < n1) ? g_s[(size_t)n * 64 + u]  : 0.f;
    }
    int pi = 0;
    for (int g = n0; g < n1; g += 4) {
        sAs[pi][j0][u] = ra;
        sS[pi][j0][u]  = rs;
        float ran, rsn;
        {
            int n = g + 4 + j0;
            ran = (n < n1) ? g_As[(size_t)n * 64 + u] : 0.f;
            rsn = (n < n1) ? g_s[(size_t)n * 64 + u]  : 0.f;
        }
        __syncthreads();
        #pragma unroll
        for (int j = 0; j < 4; j++) {
            float4 s4 = *(const float4*)&sS[pi][j][rg * 4];
            u64 s0 = pack2(s4.x, s4.x), s1 = pack2(s4.y, s4.y);
            u64 s2 = pack2(s4.z, s4.z), s3 = pack2(s4.w, s4.w);
            ulonglong2 b2v = *(const ulonglong2*)&sAs[pi][j][cg * 4];
            fma2(acc[0][0], s0, b2v.x); fma2(acc[0][1], s0, b2v.y);
            fma2(acc[1][0], s1, b2v.x); fma2(acc[1][1], s1, b2v.y);
            fma2(acc[2][0], s2, b2v.x); fma2(acc[2][1], s2, b2v.y);
            fma2(acc[3][0], s3, b2v.x); fma2(acc[3][1], s3, b2v.y);
        }
        pi ^= 1;
        ra = ran; rs = rsn;
    }
    float* base = g_part_as + (size_t)blockIdx.x * PAS_STRIDE;
    #pragma unroll
    for (int i = 0; i < 4; i++) {
        float f0, f1;
        unpack2(f0, f1, acc[i][0]);
        ((float2*)(base + (rg * 4 + i) * 64 + cg * 4))[0] = make_float2(f0, f1);
        unpack2(f0, f1, acc[i][1]);
        ((float2*)(base + (rg * 4 + i) * 64 + cg * 4))[1] = make_float2(f0, f1);
    }
}

// ---------------- K_reduce ----------------
__global__ void k_reduce() {
    int i = blockIdx.x * blockDim.x + threadIdx.x;
    if (i >= RED_SIZE) return;
    float s = 0.f;
    if (i == 16384) {
        for (int b = 0; b < NBP; b++) s += g_part_xs[(size_t)b * PXS_STRIDE + PXS_DEN];
    } else {
        int a = i >> 8, c = i & 255;
        if (c < 128) {
            int off = a * 192 + c;
            for (int b = 0; b < NBP; b++) s += g_part_xs[(size_t)b * PXS_STRIDE + off];
        } else if (c < 192) {
            int off = a * 64 + (c - 128);
            for (int b = 0; b < NBP; b++) s += g_part_as[(size_t)b * PAS_STRIDE + off];
        } else {
            int off = a * 192 + 128 + (c - 192);
            for (int b = 0; b < NBP; b++) s += g_part_xs[(size_t)b * PXS_STRIDE + off];
        }
    }
    g_red[i] = s;
}

// ---------------- K4m: mc1, o1, pruning -> M ----------------
__global__ void k_small1(float* __restrict__ out) {
    __shared__ float sadj[64 * 65];
    __shared__ float ssts[64 * 65];
    __shared__ float red[256];
    __shared__ float dsi[64];
    int t = threadIdx.x;
    for (int i = t; i < 4096; i += 256) {
        int c = i >> 6, j = i & 63;
        sadj[c * 65 + j] = g_red[c * 256 + 128 + j];
        ssts[c * 65 + j] = g_red[c * 256 + 192 + j];
    }
    __syncthreads();
    float p = 0.f;
    #pragma unroll 4
    for (int i = t; i < 4096; i += 256) {
        float v = ssts[(i >> 6) * 65 + (i & 63)];
        p += v * v;
    }
    red[t] = p; __syncthreads();
    for (int o = 128; o; o >>= 1) { if (t < o) red[t] += red[t + o]; __syncthreads(); }
    float nrm = sqrtf(red[0]); __syncthreads();
    float q = 0.f;
    #pragma unroll 4
    for (int i = t; i < 4096; i += 256) {
        int c = i >> 6, j = i & 63;
        float v = ssts[c * 65 + j] / (nrm + 1e-10f) - ((c == j) ? 0.125f : 0.f);
        q += v * v;
    }
    red[t] = q; __syncthreads();
    for (int o = 128; o; o >>= 1) { if (t < o) red[t] += red[t + o]; __syncthreads(); }
    float o1 = sqrtf(red[0]); __syncthreads();
    float tp = (t < 64) ? sadj[t * 65 + t] : 0.f;
    red[t] = tp; __syncthreads();
    for (int o = 128; o; o >>= 1) { if (t < o) red[t] += red[t + o]; __syncthreads(); }
    if (t == 0) {
        float den = g_red[16384];
        out[0] = -red[0] / (den + 1e-10f);
        out[1] = o1;
    }
    __syncthreads();
    if (t < 64) {
        float rs = 0.f;
        #pragma unroll
        for (int j = 0; j < 64; j++) if (j != t) rs += sadj[t * 65 + j];
        dsi[t] = 1.f / (sqrtf(rs) + 1e-15f);
    }
    __syncthreads();
    for (int i = t; i < 4096; i += 256) {
        int c = i >> 6, j = i & 63;
        float a = (c == j) ? 0.f : (sadj[c * 65 + j] * dsi[c] * dsi[j]);
        g_M[i] = (a > (1.0f / 63.0f)) ? 1.f : 0.f;
    }
}

// ---------------- K4a: pooled GraphConv + LN + softmax ----------------
#define L2_SMEM_FLOATS (16512*2 + 2048 + 128*4 + 16*2 + 64)

__global__ void k_layer2(const float* __restrict__ W2rel, const float* __restrict__ b2,
                         const float* __restrict__ W2root,
                         const float* __restrict__ pW2, const float* __restrict__ pb2,
                         const float* __restrict__ g2, const float* __restrict__ be2,
                         float* __restrict__ out) {
    extern __shared__ float sm2[];
    float* w2a  = sm2;
    float* w2b  = w2a + 16512;
    float* pws  = w2b + 16512;
    float* ag   = pws + 2048;
    float* pr   = ag + 128;
    float* x2r  = pr + 128;
    float* praw = x2r + 128;
    float* r16  = praw + 128;
    float* v16  = r16 + 16;
    float* Mcol = v16 + 16;
    int c = blockIdx.x;
    int t = threadIdx.x;

    for (int i = t; i < 16384; i += 128) {
        int o = i >> 7, k = i & 127;
        w2a[k * 129 + o] = W2rel[i];
        w2b[k * 129 + o] = W2root[i];
    }
    for (int i = t; i < 2048; i += 128) pws[i] = pW2[i];
    if (t < 64) Mcol[t] = g_M[t * 64 + c];
    pr[t] = g_red[c * 256 + t];
    __syncthreads();

    float a = 0.f;
    #pragma unroll 16
    for (int cp = 0; cp < 64; cp++) a += Mcol[cp] * g_red[cp * 256 + t];
    ag[t] = a;
    __syncthreads();

    float acc = __ldg(b2 + t);
    #pragma unroll 8
    for (int k = 0; k < 128; k++)
        acc += ag[k] * w2a[k * 129 + t] + pr[k] * w2b[k * 129 + t];
    acc = fmaxf(acc, 0.f);
    x2r[t] = acc;
    __syncthreads();
    {
        int j2 = t >> 3, seg = t & 7;
        float p = 0.f;
        #pragma unroll
        for (int k = seg; k < 128; k += 8) p += x2r[k] * pws[j2 * 128 + k];
        praw[t] = p;
    }
    __syncthreads();
    if (t < 16) {
        float raw = pb2[t];
        #pragma unroll
        for (int s = 0; s < 8; s++) raw += praw[t * 8 + s];
        r16[t] = raw;
    }
    __syncthreads();
    if (t < 16) {
        float mu = 0.f, sq = 0.f;
        #pragma unroll
        for (int j = 0; j < 16; j++) { mu += r16[j]; sq += r16[j] * r16[j]; }
        mu *= (1.f / 16.f);
        float var = sq * (1.f / 16.f) - mu * mu;
        v16[t] = (r16[t] - mu) * rsqrtf(var + 1e-5f) * g2[t] + be2[t];
    }
    __syncthreads();
    if (t < 16) {
        float mx = -1e30f;
        #pragma unroll
        for (int j = 0; j < 16; j++) mx = fmaxf(mx, v16[j]);
        float se = 0.f;
        #pragma unroll
        for (int j = 0; j < 16; j++) se += __expf(v16[j] - mx);
        float e = __expf(v16[t] - mx);
        out[4 + NN * 64 + c * 16 + t] = v16[t] - mx - __logf(se);
        g_s2[c * 16 + t] = e / se;
    }
}

// ---------------- K4b: dense mincut -> mc2, o2 ----------------
__global__ void k_small2(float* __restrict__ out) {
    __shared__ float sM[64 * 65];
    __shared__ float s2s[NC1 * NC2];
    __shared__ float As2[NC1 * NC2];
    __shared__ float padj[NC2 * NC2];
    __shared__ float sTs[NC2 * NC2];
    __shared__ float red[256];
    int t = threadIdx.x;
    for (int i = t; i < 4096; i += 256) sM[(i >> 6) * 65 + (i & 63)] = g_M[i];
    for (int i = t; i < 1024; i += 256) s2s[i] = g_s2[i];
    __syncthreads();
    for (int i = t; i < 1024; i += 256) {
        int c = i >> 4, j = i & 15;
        float a = 0.f;
        #pragma unroll 16
        for (int cp = 0; cp < 64; cp++) a += sM[c * 65 + cp] * s2s[cp * 16 + j];
        As2[i] = a;
    }
    __syncthreads();
    {
        int aI = t >> 4, bI = t & 15;
        float pa = 0.f, st = 0.f;
        #pragma unroll 16
        for (int c = 0; c < 64; c++) {
            float sa = s2s[c * 16 + aI];
            pa += sa * As2[c * 16 + bI];
            st += sa * s2s[c * 16 + bI];
        }
        padj[t] = pa; sTs[t] = st;
    }
    __syncthreads();
    float dp = 0.f;
    if (t < 64) {
        float d = 0.f;
        #pragma unroll
        for (int j = 0; j < 64; j++) d += sM[t * 65 + j];
        float accv = 0.f;
        #pragma unroll
        for (int j = 0; j < 16; j++) { float s = s2s[t * 16 + j]; accv += s * s; }
        dp = d * accv;
    }
    red[t] = dp; __syncthreads();
    for (int o = 128; o; o >>= 1) { if (t < o) red[t] += red[t + o]; __syncthreads(); }
    float den2 = red[0]; __syncthreads();
    float trp = (t < 16) ? padj[t * 16 + t] : 0.f;
    red[t] = trp; __syncthreads();
    for (int o = 128; o; o >>= 1) { if (t < o) red[t] += red[t + o]; __syncthreads(); }
    float tr2 = red[0]; __syncthreads();
    float np = sTs[t] * sTs[t];
    red[t] = np; __syncthreads();
    for (int o = 128; o; o >>= 1) { if (t < o) red[t] += red[t + o]; __syncthreads(); }
    float norm2 = sqrtf(red[0]); __syncthreads();
    float diff = sTs[t] / (norm2 + 1e-10f) - (((t >> 4) == (t & 15)) ? 0.25f : 0.f);
    red[t] = diff * diff; __syncthreads();
    for (int o = 128; o; o >>= 1) { if (t < o) red[t] += red[t + o]; __syncthreads(); }
    if (t == 0) {
        out[2] = -tr2 / (den2 + 1e-10f);
        out[3] = sqrtf(red[0]);
    }
}

// ---------------- launch ----------------
extern "C" void kernel_launch(void* const* d_in, const int* in_sizes, int n_in,
                              void* d_out, int out_size) {
    const float* x     = (const float*)d_in[0];
    const int*   ei    = (const int*)d_in[1];
    const float* mask  = (const float*)d_in[2];
    const float* W1rel = (const float*)d_in[3];
    const float* b1    = (const float*)d_in[4];
    const float* W1rt  = (const float*)d_in[5];
    const float* pW1   = (const float*)d_in[6];
    const float* pb1   = (const float*)d_in[7];
    const float* g1    = (const float*)d_in[8];
    const float* be1   = (const float*)d_in[9];
    const float* W2rel = (const float*)d_in[10];
    const float* b2    = (const float*)d_in[11];
    const float* W2rt  = (const float*)d_in[12];
    const float* pW2   = (const float*)d_in[13];
    const float* pb2   = (const float*)d_in[14];
    const float* g2    = (const float*)d_in[15];
    const float* be2   = (const float*)d_in[16];
    float* out = (float*)d_out;
    const int* row = ei;
    const int* col = ei + EE;

    cudaFuncSetAttribute(k_node, cudaFuncAttributeMaxDynamicSharedMemorySize,
                         K2_SMEM_FLOATS * (int)sizeof(float));
    cudaFuncSetAttribute(k_layer2, cudaFuncAttributeMaxDynamicSharedMemorySize,
                         L2_SMEM_FLOATS * (int)sizeof(float));

    k_zero<<<(NN * INC / 4 + 255) / 256, 256>>>();
    k_scatter_agg<<<(EE * 16) / 256, 256>>>(x, row, col, mask);
    k_node<<<148, K2_THREADS, K2_SMEM_FLOATS * sizeof(float)>>>(
        x, mask, W1rel, b1, W1rt, pW1, pb1, g1, be1, out);
    k_scatter_As<<<(EE * 16) / 256, 256>>>(row, col);
    k_pool_xs<<<NBP, 256>>>();
    k_pool_as<<<NBP, 256>>>();
    k_reduce<<<(RED_SIZE + 255) / 256, 256>>>();
    k_small1<<<1, 256>>>(out);
    k_layer2<<<64, 128, L2_SMEM_FLOATS * sizeof(float)>>>(W2rel, b2, W2rt, pW2, pb2, g2, be2, out);
    k_small2<<<1, 256>>>(out);
}

// round 11
// speedup vs baseline: 1.5767x; 1.2399x over previous
#include <cuda_runtime.h>

#define NN 50000
#define EE 800000
#define INC 64
#define HID 128
#define NC1 64
#define NC2 16

#define NBP 296                 // pool blocks
#define PXS_DEN 12288           // 64*192
#define PXS_STRIDE 12292        // padded
#define PAS_STRIDE 4096
#define RED_SIZE 16385

typedef unsigned long long u64;
typedef unsigned int u32;

// ---------------- scratch ----------------
__device__ __align__(256) float g_agg[NN * INC];
__device__ __align__(256) float g_x1[NN * HID];
__device__ __align__(256) float g_s[NN * NC1];
__device__ __align__(256) float g_As[NN * NC1];
__device__ __align__(256) float g_deg[NN];
__device__ __align__(256) float g_part_xs[NBP * PXS_STRIDE];
__device__ __align__(256) float g_part_as[NBP * PAS_STRIDE];
__device__ __align__(256) float g_red[16388];
__device__ __align__(256) float g_M[NC1 * NC1];
__device__ __align__(256) float g_s2[NC1 * NC2];

// ---------------- helpers ----------------
__device__ __forceinline__ void red_add_v4(float* p, float4 v) {
    asm volatile("red.global.add.v4.f32 [%0], {%1,%2,%3,%4};"
                 :: "l"(p), "f"(v.x), "f"(v.y), "f"(v.z), "f"(v.w) : "memory");
}
__device__ __forceinline__ void red_add_f32(float* p, float v) {
    asm volatile("red.global.add.f32 [%0], %1;" :: "l"(p), "f"(v) : "memory");
}
__device__ __forceinline__ u64 pack2(float x, float y) {
    u64 r; asm("mov.b64 %0, {%1, %2};" : "=l"(r) : "f"(x), "f"(y)); return r;
}
__device__ __forceinline__ void unpack2(float& x, float& y, u64 r) {
    asm("mov.b64 {%0, %1}, %2;" : "=f"(x), "=f"(y) : "l"(r));
}
__device__ __forceinline__ void fma2(u64& d, u64 a, u64 b) {
    asm("fma.rn.f32x2 %0, %1, %2, %0;" : "+l"(d) : "l"(a), "l"(b));
}
__device__ __forceinline__ u32 tf32_of(float x) {
    u32 r; asm("cvt.rna.tf32.f32 %0, %1;" : "=r"(r) : "f"(x)); return r;
}
__device__ __forceinline__ void mma_tf32(float c[4], u32 a0, u32 a1, u32 a2, u32 a3,
                                         u32 b0, u32 b1) {
    asm volatile("mma.sync.aligned.m16n8k8.row.col.f32.tf32.tf32.f32 "
                 "{%0,%1,%2,%3},{%4,%5,%6,%7},{%8,%9},{%0,%1,%2,%3};"
                 : "+f"(c[0]), "+f"(c[1]), "+f"(c[2]), "+f"(c[3])
                 : "r"(a0), "r"(a1), "r"(a2), "r"(a3), "r"(b0), "r"(b1));
}

// ---------------- K0: zero ----------------
__global__ void k_zero() {
    int i = blockIdx.x * blockDim.x + threadIdx.x;
    float4 z = make_float4(0.f, 0.f, 0.f, 0.f);
    if (i < NN * INC / 4) ((float4*)g_agg)[i] = z;
    if (i < NN * NC1 / 4) ((float4*)g_As)[i] = z;
    if (i < NN / 4)       ((float4*)g_deg)[i] = z;
}

// ---------------- K1: agg[col] += mask[row]*x[row]; deg[row] += 1 ----------------
__global__ void k_scatter_agg(const float* __restrict__ x,
                              const int* __restrict__ row,
                              const int* __restrict__ col,
                              const float* __restrict__ mask) {
    int t = blockIdx.x * blockDim.x + threadIdx.x;
    int e = t >> 4, c4 = t & 15;
    int r = __ldg(row + e);
    if (c4 == 0) red_add_f32(g_deg + r, 1.0f);
    float m = __ldg(mask + r);
    if (m != 0.f) {
        int c = __ldg(col + e);
        float4 v = __ldg((const float4*)(x + (size_t)r * INC) + c4);
        red_add_v4(g_agg + (size_t)c * INC + c4 * 4, v);
    }
}

// ---------------- K1b: A_s[row[e]] += s[col[e]] ----------------
__global__ void k_scatter_As(const int* __restrict__ row,
                             const int* __restrict__ col) {
    int t = blockIdx.x * blockDim.x + threadIdx.x;
    int e = t >> 4, c4 = t & 15;
    int r = __ldg(row + e);
    int c = __ldg(col + e);
    float4 v = __ldg((const float4*)(g_s + (size_t)c * NC1) + c4);
    red_add_v4(g_As + (size_t)r * NC1 + c4 * 4, v);
}

// ---------------- K2: tensor-core (tf32 mma.sync, 3xTF32) fused node kernel ------
// 16 nodes per warp-tile, 12 warps/block, 148 blocks.
// GEMM1: [16,128] = [16,128:agg|mask*x] @ Wcat  (3-term tf32)  -> bias+ReLU -> g_x1
// proj : [16,64]  = X1 @ pW1^T (A-frags via shuffle transform of C-frags)
// epilogue: LayerNorm + softmax + log_softmax in-fragment (4-lane shfl reductions).
// B matrices prepacked ONCE in smem in fragment order: float4 = (b0hi,b1hi,b0lo,b1lo).
#define K2_THREADS 384
#define K2_SMEM_BYTES ((8192 + 4096) * 16 + 320 * 4)

__global__ __launch_bounds__(K2_THREADS, 1)
void k_node(const float* __restrict__ x, const float* __restrict__ mask,
            const float* __restrict__ W1rel, const float* __restrict__ b1,
            const float* __restrict__ W1root,
            const float* __restrict__ pW1, const float* __restrict__ pb1,
            const float* __restrict__ g1, const float* __restrict__ be1,
            float* __restrict__ out) {
    extern __shared__ float sm[];
    float4* Bc = (float4*)sm;            // [16 kc][16 nt][32 lane] float4
    float4* Bp = Bc + 8192;              // [16 kc][ 8 nt][32 lane] float4
    float* b1s  = (float*)(Bp + 4096);   // 128
    float* pb1s = b1s + 128;             // 64
    float* g1s  = pb1s + 64;             // 64
    float* be1s = g1s + 64;              // 64

    int tid = threadIdx.x;
    // ---- prepack GEMM1 B (Wcat = [W1rel^T ; W1root^T], [128 k][128 j]) ----
    for (int i = tid; i < 8192; i += K2_THREADS) {
        int kc = i >> 9, nt = (i >> 5) & 15, L = i & 31;
        int t4 = L & 3, gr = L >> 2;
        int k0 = kc * 8 + t4, j = nt * 8 + gr;
        float w0 = (k0 < 64) ? W1rel[j * 64 + k0] : W1root[j * 64 + k0 - 64];
        float w1 = (k0 < 60) ? W1rel[j * 64 + k0 + 4] : W1root[j * 64 + k0 + 4 - 64];
        u32 h0 = tf32_of(w0), h1 = tf32_of(w1);
        u32 l0 = tf32_of(w0 - __uint_as_float(h0));
        u32 l1 = tf32_of(w1 - __uint_as_float(h1));
        Bc[i] = make_float4(__uint_as_float(h0), __uint_as_float(h1),
                            __uint_as_float(l0), __uint_as_float(l1));
    }
    // ---- prepack proj B (pW1^T: [128 k][64 jj]) ----
    for (int i = tid; i < 4096; i += K2_THREADS) {
        int kc = i >> 8, nt = (i >> 5) & 7, L = i & 31;
        int t4 = L & 3, gr = L >> 2;
        int k0 = kc * 8 + t4, jj = nt * 8 + gr;
        float w0 = pW1[jj * 128 + k0];
        float w1 = pW1[jj * 128 + k0 + 4];
        u32 h0 = tf32_of(w0), h1 = tf32_of(w1);
        u32 l0 = tf32_of(w0 - __uint_as_float(h0));
        u32 l1 = tf32_of(w1 - __uint_as_float(h1));
        Bp[i] = make_float4(__uint_as_float(h0), __uint_as_float(h1),
                            __uint_as_float(l0), __uint_as_float(l1));
    }
    if (tid < 128) b1s[tid] = b1[tid];
    if (tid < 64) { pb1s[tid] = pb1[tid]; g1s[tid] = g1[tid]; be1s[tid] = be1[tid]; }
    __syncthreads();

    int w = tid >> 5, lane = tid & 31;
    int gr = lane >> 2, t4 = lane & 3;
    int odd = t4 & 1;
    int srcA = (lane & ~3) | (t4 >> 1);
    int srcB = srcA + 2;

    int per = (NN + 147) / 148;
    int n0 = blockIdx.x * per;
    int n1 = min(n0 + per, NN);

    for (int nb = n0 + w * 16; nb < n1; nb += 12 * 16) {
        int nA = min(nb + gr, NN - 1);
        int nB = min(nb + gr + 8, NN - 1);
        float mA = __ldg(mask + nA), mB = __ldg(mask + nB);
        const float* rowAa = g_agg + (size_t)nA * 64;
        const float* rowBa = g_agg + (size_t)nB * 64;
        const float* rowAx = x + (size_t)nA * 64;
        const float* rowBx = x + (size_t)nB * 64;

        float c[16][4];
        #pragma unroll
        for (int i = 0; i < 16; i++) { c[i][0] = c[i][1] = c[i][2] = c[i][3] = 0.f; }

        // ---- GEMM1 over K=128 (8 agg kc + 8 x kc) ----
        #pragma unroll 1
        for (int kc = 0; kc < 16; kc++) {
            float a0, a1, a2, a3;
            if (kc < 8) {
                int off = kc * 8 + t4;
                a0 = __ldg(rowAa + off); a2 = __ldg(rowAa + off + 4);
                a1 = __ldg(rowBa + off); a3 = __ldg(rowBa + off + 4);
            } else {
                int off = (kc - 8) * 8 + t4;
                a0 = mA * __ldg(rowAx + off); a2 = mA * __ldg(rowAx + off + 4);
                a1 = mB * __ldg(rowBx + off); a3 = mB * __ldg(rowBx + off + 4);
            }
            u32 h0 = tf32_of(a0), h1 = tf32_of(a1), h2 = tf32_of(a2), h3 = tf32_of(a3);
            u32 l0 = tf32_of(a0 - __uint_as_float(h0));
            u32 l1 = tf32_of(a1 - __uint_as_float(h1));
            u32 l2 = tf32_of(a2 - __uint_as_float(h2));
            u32 l3 = tf32_of(a3 - __uint_as_float(h3));
            const float4* bp = Bc + kc * 512 + lane;
            #pragma unroll
            for (int nt = 0; nt < 16; nt++) {
                float4 f = bp[nt * 32];
                u32 b0h = __float_as_uint(f.x), b1h = __float_as_uint(f.y);
                u32 b0l = __float_as_uint(f.z), b1l = __float_as_uint(f.w);
                mma_tf32(c[nt], h0, h1, h2, h3, b0h, b1h);
                mma_tf32(c[nt], l0, l1, l2, l3, b0h, b1h);
                mma_tf32(c[nt], h0, h1, h2, h3, b0l, b1l);
            }
        }

        bool sA = (nb + gr) < n1;
        bool sB = (nb + gr + 8) < n1;
        float cp[8][4];
        #pragma unroll
        for (int i = 0; i < 8; i++) { cp[i][0] = cp[i][1] = cp[i][2] = cp[i][3] = 0.f; }

        // ---- finalize X1 (bias+ReLU+store) and fused proj ----
        #pragma unroll
        for (int nt = 0; nt < 16; nt++) {
            float2 bpair = *(const float2*)(b1s + nt * 8 + 2 * t4);
            float v0 = fmaxf(c[nt][0] + bpair.x, 0.f);
            float v1 = fmaxf(c[nt][1] + bpair.y, 0.f);
            float v2 = fmaxf(c[nt][2] + bpair.x, 0.f);
            float v3 = fmaxf(c[nt][3] + bpair.y, 0.f);
            if (sA) *(float2*)(g_x1 + (size_t)(nb + gr) * 128 + nt * 8 + 2 * t4) = make_float2(v0, v1);
            if (sB) *(float2*)(g_x1 + (size_t)(nb + gr + 8) * 128 + nt * 8 + 2 * t4) = make_float2(v2, v3);
            // shuffle-transform C-frag -> proj A-frag (kc' = nt)
            float x0a = __shfl_sync(0xffffffffu, v0, srcA);
            float x1a = __shfl_sync(0xffffffffu, v1, srcA);
            float a0f = odd ? x1a : x0a;
            float x0b = __shfl_sync(0xffffffffu, v0, srcB);
            float x1b = __shfl_sync(0xffffffffu, v1, srcB);
            float a2f = odd ? x1b : x0b;
            float y0a = __shfl_sync(0xffffffffu, v2, srcA);
            float y1a = __shfl_sync(0xffffffffu, v3, srcA);
            float a1f = odd ? y1a : y0a;
            float y0b = __shfl_sync(0xffffffffu, v2, srcB);
            float y1b = __shfl_sync(0xffffffffu, v3, srcB);
            float a3f = odd ? y1b : y0b;
            u32 h0 = tf32_of(a0f), h1 = tf32_of(a1f), h2 = tf32_of(a2f), h3 = tf32_of(a3f);
            u32 l0 = tf32_of(a0f - __uint_as_float(h0));
            u32 l1 = tf32_of(a1f - __uint_as_float(h1));
            u32 l2 = tf32_of(a2f - __uint_as_float(h2));
            u32 l3 = tf32_of(a3f - __uint_as_float(h3));
            const float4* bq = Bp + nt * 256 + lane;
            #pragma unroll
            for (int np = 0; np < 8; np++) {
                float4 f = bq[np * 32];
                u32 b0h = __float_as_uint(f.x), b1h = __float_as_uint(f.y);
                u32 b0l = __float_as_uint(f.z), b1l = __float_as_uint(f.w);
                mma_tf32(cp[np], h0, h1, h2, h3, b0h, b1h);
                mma_tf32(cp[np], l0, l1, l2, l3, b0h, b1h);
                mma_tf32(cp[np], h0, h1, h2, h3, b0l, b1l);
            }
        }

        // ---- epilogue: +pb1, LayerNorm(64), softmax / log_softmax ----
        float sumA = 0.f, sqA = 0.f, sumB = 0.f, sqB = 0.f;
        #pragma unroll
        for (int p = 0; p < 8; p++) {
            float2 pb = *(const float2*)(pb1s + p * 8 + 2 * t4);
            cp[p][0] += pb.x; cp[p][1] += pb.y;
            cp[p][2] += pb.x; cp[p][3] += pb.y;
            sumA += cp[p][0] + cp[p][1]; sqA += cp[p][0]*cp[p][0] + cp[p][1]*cp[p][1];
            sumB += cp[p][2] + cp[p][3]; sqB += cp[p][2]*cp[p][2] + cp[p][3]*cp[p][3];
        }
        #pragma unroll
        for (int o = 1; o <= 2; o <<= 1) {
            sumA += __shfl_xor_sync(0xffffffffu, sumA, o);
            sqA  += __shfl_xor_sync(0xffffffffu, sqA, o);
            sumB += __shfl_xor_sync(0xffffffffu, sumB, o);
            sqB  += __shfl_xor_sync(0xffffffffu, sqB, o);
        }
        float muA = sumA * (1.f/64.f), varA = sqA * (1.f/64.f) - muA * muA;
        float muB = sumB * (1.f/64.f), varB = sqB * (1.f/64.f) - muB * muB;
        float invA = rsqrtf(varA + 1e-5f), invB = rsqrtf(varB + 1e-5f);
        float mxA = -1e30f, mxB = -1e30f;
        #pragma unroll
        for (int p = 0; p < 8; p++) {
            float2 gp = *(const float2*)(g1s + p * 8 + 2 * t4);
            float2 bp2 = *(const float2*)(be1s + p * 8 + 2 * t4);
            cp[p][0] = (cp[p][0] - muA) * invA * gp.x + bp2.x;
            cp[p][1] = (cp[p][1] - muA) * invA * gp.y + bp2.y;
            cp[p][2] = (cp[p][2] - muB) * invB * gp.x + bp2.x;
            cp[p][3] = (cp[p][3] - muB) * invB * gp.y + bp2.y;
            mxA = fmaxf(mxA, fmaxf(cp[p][0], cp[p][1]));
            mxB = fmaxf(mxB, fmaxf(cp[p][2], cp[p][3]));
        }
        #pragma unroll
        for (int o = 1; o <= 2; o <<= 1) {
            mxA = fmaxf(mxA, __shfl_xor_sync(0xffffffffu, mxA, o));
            mxB = fmaxf(mxB, __shfl_xor_sync(0xffffffffu, mxB, o));
        }
        float seA = 0.f, seB = 0.f;
        #pragma unroll
        for (int p = 0; p < 8; p++) {
            seA += __expf(cp[p][0] - mxA) + __expf(cp[p][1] - mxA);
            seB += __expf(cp[p][2] - mxB) + __expf(cp[p][3] - mxB);
        }
        #pragma unroll
        for (int o = 1; o <= 2; o <<= 1) {
            seA += __shfl_xor_sync(0xffffffffu, seA, o);
            seB += __shfl_xor_sync(0xffffffffu, seB, o);
        }
        float lseA = __logf(seA), lseB = __logf(seB);
        float rA = 1.f / seA, rB = 1.f / seB;
        #pragma unroll
        for (int p = 0; p < 8; p++) {
            int colo = p * 8 + 2 * t4;
            if (sA) {
                *(float2*)(out + 4 + (size_t)(nb + gr) * 64 + colo) =
                    make_float2(cp[p][0] - mxA - lseA, cp[p][1] - mxA - lseA);
                *(float2*)(g_s + (size_t)(nb + gr) * 64 + colo) =
                    make_float2(__expf(cp[p][0] - mxA) * rA, __expf(cp[p][1] - mxA) * rA);
            }
            if (sB) {
                *(float2*)(out + 4 + (size_t)(nb + gr + 8) * 64 + colo) =
                    make_float2(cp[p][2] - mxB - lseB, cp[p][3] - mxB - lseB);
                *(float2*)(g_s + (size_t)(nb + gr + 8) * 64 + colo) =
                    make_float2(__expf(cp[p][2] - mxB) * rB, __expf(cp[p][3] - mxB) * rB);
            }
        }
    }
}

// ---------------- K_pool_xs: s^T @ [x1 | s] (64x192) + mincut denominator -------
__global__ void k_pool_xs() {
    __shared__ __align__(16) float vv[2][4][192];
    __shared__ float redsh[256];
    int t = threadIdx.x;
    int rg = t >> 4, cg = t & 15;
    int per = (NN + NBP - 1) / NBP;
    int n0 = blockIdx.x * per;
    int n1 = min(n0 + per, NN);

    const float* src;
    int stride;
    if (t < 128)      { src = g_x1 + t;         stride = 128; }
    else if (t < 192) { src = g_s + (t - 128);  stride = 64; }
    else              { src = g_s + (t - 192);  stride = 64; }

    u64 acc[4][6];
    #pragma unroll
    for (int i = 0; i < 4; i++)
        #pragma unroll
        for (int j = 0; j < 6; j++) acc[i][j] = 0ULL;
    float denp = 0.f;

    float r[4], dg[4];
    #pragma unroll
    for (int j = 0; j < 4; j++) {
        int n = n0 + j;
        r[j]  = (n < n1) ? src[(size_t)n * stride] : 0.f;
        dg[j] = (t >= 192 && n < n1) ? __ldg(g_deg + n) : 0.f;
    }
    int pi = 0;
    for (int g = n0; g < n1; g += 4) {
        if (t < 192) {
            #pragma unroll
            for (int j = 0; j < 4; j++) vv[pi][j][t] = r[j];
        } else {
            #pragma unroll
            for (int j = 0; j < 4; j++) denp += dg[j] * r[j] * r[j];
        }
        float rn[4], dn[4];
        #pragma unroll
        for (int j = 0; j < 4; j++) {
            int n = g + 4 + j;
            rn[j] = (n < n1) ? src[(size_t)n * stride] : 0.f;
            dn[j] = (t >= 192 && n < n1) ? __ldg(g_deg + n) : 0.f;
        }
        __syncthreads();
        #pragma unroll
        for (int j = 0; j < 4; j++) {
            float4 s4 = *(const float4*)&vv[pi][j][128 + rg * 4];
            u64 s0 = pack2(s4.x, s4.x), s1 = pack2(s4.y, s4.y);
            u64 s2 = pack2(s4.z, s4.z), s3 = pack2(s4.w, s4.w);
            const ulonglong2* vp = (const ulonglong2*)&vv[pi][j][cg * 12];
            #pragma unroll
            for (int h = 0; h < 3; h++) {
                ulonglong2 b2v = vp[h];
                fma2(acc[0][2*h], s0, b2v.x); fma2(acc[0][2*h+1], s0, b2v.y);
                fma2(acc[1][2*h], s1, b2v.x); fma2(acc[1][2*h+1], s1, b2v.y);
                fma2(acc[2][2*h], s2, b2v.x); fma2(acc[2][2*h+1], s2, b2v.y);
                fma2(acc[3][2*h], s3, b2v.x); fma2(acc[3][2*h+1], s3, b2v.y);
            }
        }
        pi ^= 1;
        #pragma unroll
        for (int j = 0; j < 4; j++) { r[j] = rn[j]; dg[j] = dn[j]; }
    }
    float* base = g_part_xs + (size_t)blockIdx.x * PXS_STRIDE;
    #pragma unroll
    for (int i = 0; i < 4; i++)
        #pragma unroll
        for (int j = 0; j < 6; j++) {
            float f0, f1;
            unpack2(f0, f1, acc[i][j]);
            ((float2*)(base + (rg * 4 + i) * 192 + cg * 12))[j] = make_float2(f0, f1);
        }
    redsh[t] = denp; __syncthreads();
    for (int o = 128; o; o >>= 1) { if (t < o) redsh[t] += redsh[t + o]; __syncthreads(); }
    if (t == 0) base[PXS_DEN] = redsh[0];
}

// ---------------- K_pool_as: s^T @ A_s (64x64) ----------------
__global__ void k_pool_as() {
    __shared__ __align__(16) float sAs[2][4][64];
    __shared__ __align__(16) float sS[2][4][64];
    int t = threadIdx.x;
    int rg = t >> 4, cg = t & 15;
    int j0 = t >> 6, u = t & 63;
    int per = (NN + NBP - 1) / NBP;
    int n0 = blockIdx.x * per;
    int n1 = min(n0 + per, NN);

    u64 acc[4][2];
    #pragma unroll
    for (int i = 0; i < 4; i++) { acc[i][0] = 0ULL; acc[i][1] = 0ULL; }

    float ra, rs;
    {
        int n = n0 + j0;
        ra = (n < n1) ? g_As[(size_t)n * 64 + u] : 0.f;
        rs = (n < n1) ? g_s[(size_t)n * 64 + u]  : 0.f;
    }
    int pi = 0;
    for (int g = n0; g < n1; g += 4) {
        sAs[pi][j0][u] = ra;
        sS[pi][j0][u]  = rs;
        float ran, rsn;
        {
            int n = g + 4 + j0;
            ran = (n < n1) ? g_As[(size_t)n * 64 + u] : 0.f;
            rsn = (n < n1) ? g_s[(size_t)n * 64 + u]  : 0.f;
        }
        __syncthreads();
        #pragma unroll
        for (int j = 0; j < 4; j++) {
            float4 s4 = *(const float4*)&sS[pi][j][rg * 4];
            u64 s0 = pack2(s4.x, s4.x), s1 = pack2(s4.y, s4.y);
            u64 s2 = pack2(s4.z, s4.z), s3 = pack2(s4.w, s4.w);
            ulonglong2 b2v = *(const ulonglong2*)&sAs[pi][j][cg * 4];
            fma2(acc[0][0], s0, b2v.x); fma2(acc[0][1], s0, b2v.y);
            fma2(acc[1][0], s1, b2v.x); fma2(acc[1][1], s1, b2v.y);
            fma2(acc[2][0], s2, b2v.x); fma2(acc[2][1], s2, b2v.y);
            fma2(acc[3][0], s3, b2v.x); fma2(acc[3][1], s3, b2v.y);
        }
        pi ^= 1;
        ra = ran; rs = rsn;
    }
    float* base = g_part_as + (size_t)blockIdx.x * PAS_STRIDE;
    #pragma unroll
    for (int i = 0; i < 4; i++) {
        float f0, f1;
        unpack2(f0, f1, acc[i][0]);
        ((float2*)(base + (rg * 4 + i) * 64 + cg * 4))[0] = make_float2(f0, f1);
        unpack2(f0, f1, acc[i][1]);
        ((float2*)(base + (rg * 4 + i) * 64 + cg * 4))[1] = make_float2(f0, f1);
    }
}

// ---------------- K_reduce ----------------
__global__ void k_reduce() {
    int i = blockIdx.x * blockDim.x + threadIdx.x;
    if (i >= RED_SIZE) return;
    float s = 0.f;
    if (i == 16384) {
        for (int b = 0; b < NBP; b++) s += g_part_xs[(size_t)b * PXS_STRIDE + PXS_DEN];
    } else {
        int a = i >> 8, c = i & 255;
        if (c < 128) {
            int off = a * 192 + c;
            for (int b = 0; b < NBP; b++) s += g_part_xs[(size_t)b * PXS_STRIDE + off];
        } else if (c < 192) {
            int off = a * 64 + (c - 128);
            for (int b = 0; b < NBP; b++) s += g_part_as[(size_t)b * PAS_STRIDE + off];
        } else {
            int off = a * 192 + 128 + (c - 192);
            for (int b = 0; b < NBP; b++) s += g_part_xs[(size_t)b * PXS_STRIDE + off];
        }
    }
    g_red[i] = s;
}

// ---------------- K4m: mc1, o1, pruning -> M ----------------
__global__ void k_small1(float* __restrict__ out) {
    __shared__ float sadj[64 * 65];
    __shared__ float ssts[64 * 65];
    __shared__ float red[256];
    __shared__ float dsi[64];
    int t = threadIdx.x;
    for (int i = t; i < 4096; i += 256) {
        int c = i >> 6, j = i & 63;
        sadj[c * 65 + j] = g_red[c * 256 + 128 + j];
        ssts[c * 65 + j] = g_red[c * 256 + 192 + j];
    }
    __syncthreads();
    float p = 0.f;
    #pragma unroll 4
    for (int i = t; i < 4096; i += 256) {
        float v = ssts[(i >> 6) * 65 + (i & 63)];
        p += v * v;
    }
    red[t] = p; __syncthreads();
    for (int o = 128; o; o >>= 1) { if (t < o) red[t] += red[t + o]; __syncthreads(); }
    float nrm = sqrtf(red[0]); __syncthreads();
    float q = 0.f;
    #pragma unroll 4
    for (int i = t; i < 4096; i += 256) {
        int c = i >> 6, j = i & 63;
        float v = ssts[c * 65 + j] / (nrm + 1e-10f) - ((c == j) ? 0.125f : 0.f);
        q += v * v;
    }
    red[t] = q; __syncthreads();
    for (int o = 128; o; o >>= 1) { if (t < o) red[t] += red[t + o]; __syncthreads(); }
    float o1 = sqrtf(red[0]); __syncthreads();
    float tp = (t < 64) ? sadj[t * 65 + t] : 0.f;
    red[t] = tp; __syncthreads();
    for (int o = 128; o; o >>= 1) { if (t < o) red[t] += red[t + o]; __syncthreads(); }
    if (t == 0) {
        float den = g_red[16384];
        out[0] = -red[0] / (den + 1e-10f);
        out[1] = o1;
    }
    __syncthreads();
    if (t < 64) {
        float rs = 0.f;
        #pragma unroll
        for (int j = 0; j < 64; j++) if (j != t) rs += sadj[t * 65 + j];
        dsi[t] = 1.f / (sqrtf(rs) + 1e-15f);
    }
    __syncthreads();
    for (int i = t; i < 4096; i += 256) {
        int c = i >> 6, j = i & 63;
        float a = (c == j) ? 0.f : (sadj[c * 65 + j] * dsi[c] * dsi[j]);
        g_M[i] = (a > (1.0f / 63.0f)) ? 1.f : 0.f;
    }
}

// ---------------- K4a: pooled GraphConv + LN + softmax ----------------
#define L2_SMEM_FLOATS (16512*2 + 2048 + 128*4 + 16*2 + 64)

__global__ void k_layer2(const float* __restrict__ W2rel, const float* __restrict__ b2,
                         const float* __restrict__ W2root,
                         const float* __restrict__ pW2, const float* __restrict__ pb2,
                         const float* __restrict__ g2, const float* __restrict__ be2,
                         float* __restrict__ out) {
    extern __shared__ float sm2[];
    float* w2a  = sm2;
    float* w2b  = w2a + 16512;
    float* pws  = w2b + 16512;
    float* ag   = pws + 2048;
    float* pr   = ag + 128;
    float* x2r  = pr + 128;
    float* praw = x2r + 128;
    float* r16  = praw + 128;
    float* v16  = r16 + 16;
    float* Mcol = v16 + 16;
    int c = blockIdx.x;
    int t = threadIdx.x;

    for (int i = t; i < 16384; i += 128) {
        int o = i >> 7, k = i & 127;
        w2a[k * 129 + o] = W2rel[i];
        w2b[k * 129 + o] = W2root[i];
    }
    for (int i = t; i < 2048; i += 128) pws[i] = pW2[i];
    if (t < 64) Mcol[t] = g_M[t * 64 + c];
    pr[t] = g_red[c * 256 + t];
    __syncthreads();

    float a = 0.f;
    #pragma unroll 16
    for (int cp = 0; cp < 64; cp++) a += Mcol[cp] * g_red[cp * 256 + t];
    ag[t] = a;
    __syncthreads();

    float acc = __ldg(b2 + t);
    #pragma unroll 8
    for (int k = 0; k < 128; k++)
        acc += ag[k] * w2a[k * 129 + t] + pr[k] * w2b[k * 129 + t];
    acc = fmaxf(acc, 0.f);
    x2r[t] = acc;
    __syncthreads();
    {
        int j2 = t >> 3, seg = t & 7;
        float p = 0.f;
        #pragma unroll
        for (int k = seg; k < 128; k += 8) p += x2r[k] * pws[j2 * 128 + k];
        praw[t] = p;
    }
    __syncthreads();
    if (t < 16) {
        float raw = pb2[t];
        #pragma unroll
        for (int s = 0; s < 8; s++) raw += praw[t * 8 + s];
        r16[t] = raw;
    }
    __syncthreads();
    if (t < 16) {
        float mu = 0.f, sq = 0.f;
        #pragma unroll
        for (int j = 0; j < 16; j++) { mu += r16[j]; sq += r16[j] * r16[j]; }
        mu *= (1.f / 16.f);
        float var = sq * (1.f / 16.f) - mu * mu;
        v16[t] = (r16[t] - mu) * rsqrtf(var + 1e-5f) * g2[t] + be2[t];
    }
    __syncthreads();
    if (t < 16) {
        float mx = -1e30f;
        #pragma unroll
        for (int j = 0; j < 16; j++) mx = fmaxf(mx, v16[j]);
        float se = 0.f;
        #pragma unroll
        for (int j = 0; j < 16; j++) se += __expf(v16[j] - mx);
        float e = __expf(v16[t] - mx);
        out[4 + NN * 64 + c * 16 + t] = v16[t] - mx - __logf(se);
        g_s2[c * 16 + t] = e / se;
    }
}

// ---------------- K4b: dense mincut -> mc2, o2 ----------------
__global__ void k_small2(float* __restrict__ out) {
    __shared__ float sM[64 * 65];
    __shared__ float s2s[NC1 * NC2];
    __shared__ float As2[NC1 * NC2];
    __shared__ float padj[NC2 * NC2];
    __shared__ float sTs[NC2 * NC2];
    __shared__ float red[256];
    int t = threadIdx.x;
    for (int i = t; i < 4096; i += 256) sM[(i >> 6) * 65 + (i & 63)] = g_M[i];
    for (int i = t; i < 1024; i += 256) s2s[i] = g_s2[i];
    __syncthreads();
    for (int i = t; i < 1024; i += 256) {
        int c = i >> 4, j = i & 15;
        float a = 0.f;
        #pragma unroll 16
        for (int cp = 0; cp < 64; cp++) a += sM[c * 65 + cp] * s2s[cp * 16 + j];
        As2[i] = a;
    }
    __syncthreads();
    {
        int aI = t >> 4, bI = t & 15;
        float pa = 0.f, st = 0.f;
        #pragma unroll 16
        for (int c = 0; c < 64; c++) {
            float sa = s2s[c * 16 + aI];
            pa += sa * As2[c * 16 + bI];
            st += sa * s2s[c * 16 + bI];
        }
        padj[t] = pa; sTs[t] = st;
    }
    __syncthreads();
    float dp = 0.f;
    if (t < 64) {
        float d = 0.f;
        #pragma unroll
        for (int j = 0; j < 64; j++) d += sM[t * 65 + j];
        float accv = 0.f;
        #pragma unroll
        for (int j = 0; j < 16; j++) { float s = s2s[t * 16 + j]; accv += s * s; }
        dp = d * accv;
    }
    red[t] = dp; __syncthreads();
    for (int o = 128; o; o >>= 1) { if (t < o) red[t] += red[t + o]; __syncthreads(); }
    float den2 = red[0]; __syncthreads();
    float trp = (t < 16) ? padj[t * 16 + t] : 0.f;
    red[t] = trp; __syncthreads();
    for (int o = 128; o; o >>= 1) { if (t < o) red[t] += red[t + o]; __syncthreads(); }
    float tr2 = red[0]; __syncthreads();
    float np = sTs[t] * sTs[t];
    red[t] = np; __syncthreads();
    for (int o = 128; o; o >>= 1) { if (t < o) red[t] += red[t + o]; __syncthreads(); }
    float norm2 = sqrtf(red[0]); __syncthreads();
    float diff = sTs[t] / (norm2 + 1e-10f) - (((t >> 4) == (t & 15)) ? 0.25f : 0.f);
    red[t] = diff * diff; __syncthreads();
    for (int o = 128; o; o >>= 1) { if (t < o) red[t] += red[t + o]; __syncthreads(); }
    if (t == 0) {
        out[2] = -tr2 / (den2 + 1e-10f);
        out[3] = sqrtf(red[0]);
    }
}

// ---------------- launch ----------------
extern "C" void kernel_launch(void* const* d_in, const int* in_sizes, int n_in,
                              void* d_out, int out_size) {
    const float* x     = (const float*)d_in[0];
    const int*   ei    = (const int*)d_in[1];
    const float* mask  = (const float*)d_in[2];
    const float* W1rel = (const float*)d_in[3];
    const float* b1    = (const float*)d_in[4];
    const float* W1rt  = (const float*)d_in[5];
    const float* pW1   = (const float*)d_in[6];
    const float* pb1   = (const float*)d_in[7];
    const float* g1    = (const float*)d_in[8];
    const float* be1   = (const float*)d_in[9];
    const float* W2rel = (const float*)d_in[10];
    const float* b2    = (const float*)d_in[11];
    const float* W2rt  = (const float*)d_in[12];
    const float* pW2   = (const float*)d_in[13];
    const float* pb2   = (const float*)d_in[14];
    const float* g2    = (const float*)d_in[15];
    const float* be2   = (const float*)d_in[16];
    float* out = (float*)d_out;
    const int* row = ei;
    const int* col = ei + EE;

    cudaFuncSetAttribute(k_node, cudaFuncAttributeMaxDynamicSharedMemorySize,
                         K2_SMEM_BYTES);
    cudaFuncSetAttribute(k_layer2, cudaFuncAttributeMaxDynamicSharedMemorySize,
                         L2_SMEM_FLOATS * (int)sizeof(float));

    k_zero<<<(NN * INC / 4 + 255) / 256, 256>>>();
    k_scatter_agg<<<(EE * 16) / 256, 256>>>(x, row, col, mask);
    k_node<<<148, K2_THREADS, K2_SMEM_BYTES>>>(
        x, mask, W1rel, b1, W1rt, pW1, pb1, g1, be1, out);
    k_scatter_As<<<(EE * 16) / 256, 256>>>(row, col);
    k_pool_xs<<<NBP, 256>>>();
    k_pool_as<<<NBP, 256>>>();
    k_reduce<<<(RED_SIZE + 255) / 256, 256>>>();
    k_small1<<<1, 256>>>(out);
    k_layer2<<<64, 128, L2_SMEM_FLOATS * sizeof(float)>>>(W2rel, b2, W2rt, pW2, pb2, g2, be2, out);
    k_small2<<<1, 256>>>(out);
}

// round 14
// speedup vs baseline: 1.6662x; 1.0568x over previous
#include <cuda_runtime.h>
#include <cuda_bf16.h>

#define NN 50000
#define EE 800000
#define INC 64
#define HID 128
#define NC1 64
#define NC2 16

#define NBP 296
#define PXS_DEN 12288
#define PXS_STRIDE 12292
#define PAS_STRIDE 4096
#define RED_SIZE 16385

typedef unsigned long long u64;
typedef unsigned int u32;

// ---------------- scratch ----------------
__device__ __align__(256) float g_agg[NN * INC];
__device__ __align__(256) float g_x1[NN * HID];
__device__ __align__(256) float g_s[NN * NC1];
__device__ __align__(256) float g_As[NN * NC1];
__device__ __align__(256) float g_deg[NN];
__device__ __align__(256) float g_part_xs[NBP * PXS_STRIDE];
__device__ __align__(256) float g_part_as[NBP * PAS_STRIDE];
__device__ __align__(256) float g_red[16388];
__device__ __align__(256) float g_M[NC1 * NC1];
__device__ __align__(256) float g_s2[NC1 * NC2];

// ---------------- helpers ----------------
__device__ __forceinline__ void red_add_v4(float* p, float4 v) {
    asm volatile("red.global.add.v4.f32 [%0], {%1,%2,%3,%4};"
                 :: "l"(p), "f"(v.x), "f"(v.y), "f"(v.z), "f"(v.w) : "memory");
}
__device__ __forceinline__ void red_add_f32(float* p, float v) {
    asm volatile("red.global.add.f32 [%0], %1;" :: "l"(p), "f"(v) : "memory");
}
__device__ __forceinline__ u64 pack2(float x, float y) {
    u64 r; asm("mov.b64 %0, {%1, %2};" : "=l"(r) : "f"(x), "f"(y)); return r;
}
__device__ __forceinline__ void unpack2(float& x, float& y, u64 r) {
    asm("mov.b64 {%0, %1}, %2;" : "=f"(x), "=f"(y) : "l"(r));
}
__device__ __forceinline__ void fma2(u64& d, u64 a, u64 b) {
    asm("fma.rn.f32x2 %0, %1, %2, %0;" : "+l"(d) : "l"(a), "l"(b));
}
// pack bf16(a) into lo half, bf16(b) into hi half; also emit the lo-residual pack
__device__ __forceinline__ void bf16_hl(float a, float b, u32& hi, u32& lo) {
    float ah = __bfloat162float(__float2bfloat16(a));
    float bh = __bfloat162float(__float2bfloat16(b));
    asm("cvt.rn.bf16x2.f32 %0, %1, %2;" : "=r"(hi) : "f"(bh), "f"(ah));
    asm("cvt.rn.bf16x2.f32 %0, %1, %2;" : "=r"(lo) : "f"(b - bh), "f"(a - ah));
}
__device__ __forceinline__ void mma_bf16(float c[4], u32 a0, u32 a1, u32 a2, u32 a3,
                                         u32 b0, u32 b1) {
    asm volatile("mma.sync.aligned.m16n8k16.row.col.f32.bf16.bf16.f32 "
                 "{%0,%1,%2,%3},{%4,%5,%6,%7},{%8,%9},{%0,%1,%2,%3};"
                 : "+f"(c[0]), "+f"(c[1]), "+f"(c[2]), "+f"(c[3])
                 : "r"(a0), "r"(a1), "r"(a2), "r"(a3), "r"(b0), "r"(b1));
}

// ---------------- K0: zero ----------------
__global__ void k_zero() {
    int i = blockIdx.x * blockDim.x + threadIdx.x;
    float4 z = make_float4(0.f, 0.f, 0.f, 0.f);
    if (i < NN * INC / 4) ((float4*)g_agg)[i] = z;
    if (i < NN * NC1 / 4) ((float4*)g_As)[i] = z;
    if (i < NN / 4)       ((float4*)g_deg)[i] = z;
}

// ---------------- K1: agg[col] += mask[row]*x[row]; deg[row] += 1 ----------------
__global__ void k_scatter_agg(const float* __restrict__ x,
                              const int* __restrict__ row,
                              const int* __restrict__ col,
                              const float* __restrict__ mask) {
    int t = blockIdx.x * blockDim.x + threadIdx.x;
    int e = t >> 4, c4 = t & 15;
    int r = __ldg(row + e);
    if (c4 == 0) red_add_f32(g_deg + r, 1.0f);
    float m = __ldg(mask + r);
    if (m != 0.f) {
        int c = __ldg(col + e);
        float4 v = __ldg((const float4*)(x + (size_t)r * INC) + c4);
        red_add_v4(g_agg + (size_t)c * INC + c4 * 4, v);
    }
}

// ---------------- K1b: A_s[row[e]] += s[col[e]] ----------------
__global__ void k_scatter_As(const int* __restrict__ row,
                             const int* __restrict__ col) {
    int t = blockIdx.x * blockDim.x + threadIdx.x;
    int e = t >> 4, c4 = t & 15;
    int r = __ldg(row + e);
    int c = __ldg(col + e);
    float4 v = __ldg((const float4*)(g_s + (size_t)c * NC1) + c4);
    red_add_v4(g_As + (size_t)r * NC1 + c4 * 4, v);
}

// ---------------- K2: bf16 m16n8k16 (3-term split) fused node kernel ------------
// 16 nodes per warp-tile, 12 warps/block, 148 blocks.
// GEMM1: [16,128] = [16,128:agg|mask*x] @ Wcat, 3-term bf16 -> bias+ReLU -> g_x1
// proj : A-frags for chunk kc' are EXACTLY C-frags of tiles 2kc',2kc'+1 (no shuffles)
// epilogue: LayerNorm + softmax + log_softmax in-fragment (4-lane shfl reductions).
#define K2_THREADS 384
#define K2_SMEM_BYTES (4096*16 + 2048*16 + 320*4)

__global__ __launch_bounds__(K2_THREADS, 1)
void k_node(const float* __restrict__ x, const float* __restrict__ mask,
            const float* __restrict__ W1rel, const float* __restrict__ b1,
            const float* __restrict__ W1root,
            const float* __restrict__ pW1, const float* __restrict__ pb1,
            const float* __restrict__ g1, const float* __restrict__ be1,
            float* __restrict__ out) {
    extern __shared__ float sm[];
    float4* Bc = (float4*)sm;            // [8 kc][16 nt][32 lane] (b0h,b1h,b0l,b1l)
    float4* Bp = Bc + 4096;              // [8 kc][ 8 np][32 lane]
    float* b1s  = (float*)(Bp + 2048);   // 128
    float* pb1s = b1s + 128;             // 64
    float* g1s  = pb1s + 64;             // 64
    float* be1s = g1s + 64;              // 64

    int tid = threadIdx.x;
    // ---- prepack GEMM1 B: Wcat[k][j], K=128 (rel 0-63 | root 64-127), J=128 ----
    for (int i = tid; i < 4096; i += K2_THREADS) {
        int kc = i >> 9, nt = (i >> 5) & 15, L = i & 31;
        int t4 = L & 3, gr = L >> 2;
        int j = nt * 8 + gr;
        int kk = (kc & 3) * 16 + 2 * t4;
        const float* src = (kc < 4) ? W1rel : W1root;
        float w00 = src[j * 64 + kk],     w01 = src[j * 64 + kk + 1];
        float w10 = src[j * 64 + kk + 8], w11 = src[j * 64 + kk + 9];
        u32 b0h, b0l, b1h, b1l;
        bf16_hl(w00, w01, b0h, b0l);
        bf16_hl(w10, w11, b1h, b1l);
        Bc[i] = make_float4(__uint_as_float(b0h), __uint_as_float(b1h),
                            __uint_as_float(b0l), __uint_as_float(b1l));
    }
    // ---- prepack proj B: pW1^T [128 k][64 j] ----
    for (int i = tid; i < 2048; i += K2_THREADS) {
        int kc = i >> 8, np = (i >> 5) & 7, L = i & 31;
        int t4 = L & 3, gr = L >> 2;
        int j = np * 8 + gr;
        int kk = kc * 16 + 2 * t4;
        float w00 = pW1[j * 128 + kk],     w01 = pW1[j * 128 + kk + 1];
        float w10 = pW1[j * 128 + kk + 8], w11 = pW1[j * 128 + kk + 9];
        u32 b0h, b0l, b1h, b1l;
        bf16_hl(w00, w01, b0h, b0l);
        bf16_hl(w10, w11, b1h, b1l);
        Bp[i] = make_float4(__uint_as_float(b0h), __uint_as_float(b1h),
                            __uint_as_float(b0l), __uint_as_float(b1l));
    }
    if (tid < 128) b1s[tid] = b1[tid];
    if (tid < 64) { pb1s[tid] = pb1[tid]; g1s[tid] = g1[tid]; be1s[tid] = be1[tid]; }
    __syncthreads();

    int w = tid >> 5, lane = tid & 31;
    int gr = lane >> 2, t4 = lane & 3;

    int per = (NN + 147) / 148;
    int n0 = blockIdx.x * per;
    int n1 = min(n0 + per, NN);

    for (int nb = n0 + w * 16; nb < n1; nb += 12 * 16) {
        int nA = min(nb + gr, NN - 1);
        int nB = min(nb + gr + 8, NN - 1);
        float mA = __ldg(mask + nA), mB = __ldg(mask + nB);
        const float2* rAa = (const float2*)(g_agg + (size_t)nA * 64);
        const float2* rBa = (const float2*)(g_agg + (size_t)nB * 64);
        const float2* rAx = (const float2*)(x + (size_t)nA * 64);
        const float2* rBx = (const float2*)(x + (size_t)nB * 64);

        float c[16][4];
        #pragma unroll
        for (int i = 0; i < 16; i++) { c[i][0] = c[i][1] = c[i][2] = c[i][3] = 0.f; }

        // ---- GEMM1 over K=128 in 8 chunks of 16 (4 agg + 4 masked-x) ----
        #pragma unroll 1
        for (int kc = 0; kc < 8; kc++) {
            int idx = (kc & 3) * 8 + t4;          // float2 index
            float2 fA0, fA1, fB0, fB1;
            if (kc < 4) {
                fA0 = __ldg(rAa + idx); fA1 = __ldg(rAa + idx + 4);
                fB0 = __ldg(rBa + idx); fB1 = __ldg(rBa + idx + 4);
            } else {
                fA0 = __ldg(rAx + idx); fA1 = __ldg(rAx + idx + 4);
                fB0 = __ldg(rBx + idx); fB1 = __ldg(rBx + idx + 4);
                fA0.x *= mA; fA0.y *= mA; fA1.x *= mA; fA1.y *= mA;
                fB0.x *= mB; fB0.y *= mB; fB1.x *= mB; fB1.y *= mB;
            }
            u32 a0h, a0l, a1h, a1l, a2h, a2l, a3h, a3l;
            bf16_hl(fA0.x, fA0.y, a0h, a0l);
            bf16_hl(fB0.x, fB0.y, a1h, a1l);
            bf16_hl(fA1.x, fA1.y, a2h, a2l);
            bf16_hl(fB1.x, fB1.y, a3h, a3l);
            const float4* bp = Bc + kc * 512 + lane;
            #pragma unroll
            for (int nt = 0; nt < 16; nt++) {
                float4 f = bp[nt * 32];
                u32 b0h = __float_as_uint(f.x), b1h = __float_as_uint(f.y);
                u32 b0l = __float_as_uint(f.z), b1l = __float_as_uint(f.w);
                mma_bf16(c[nt], a0h, a1h, a2h, a3h, b0h, b1h);
                mma_bf16(c[nt], a0l, a1l, a2l, a3l, b0h, b1h);
                mma_bf16(c[nt], a0h, a1h, a2h, a3h, b0l, b1l);
            }
        }

        bool sA = (nb + gr) < n1;
        bool sB = (nb + gr + 8) < n1;
        float cp[8][4];
        #pragma unroll
        for (int i = 0; i < 8; i++) { cp[i][0] = cp[i][1] = cp[i][2] = cp[i][3] = 0.f; }

        // ---- finalize X1 (bias+ReLU+store) and fused proj, no shuffles ----
        #pragma unroll
        for (int kcp = 0; kcp < 8; kcp++) {
            u32 a0h, a0l, a1h, a1l, a2h, a2l, a3h, a3l;
            {   // nt = 2*kcp  -> k pair [kcp*16 + 2*t4]
                int nt = 2 * kcp;
                float2 bpair = *(const float2*)(b1s + nt * 8 + 2 * t4);
                float v0 = fmaxf(c[nt][0] + bpair.x, 0.f);
                float v1 = fmaxf(c[nt][1] + bpair.y, 0.f);
                float v2 = fmaxf(c[nt][2] + bpair.x, 0.f);
                float v3 = fmaxf(c[nt][3] + bpair.y, 0.f);
                if (sA) *(float2*)(g_x1 + (size_t)(nb + gr) * 128 + nt * 8 + 2 * t4) = make_float2(v0, v1);
                if (sB) *(float2*)(g_x1 + (size_t)(nb + gr + 8) * 128 + nt * 8 + 2 * t4) = make_float2(v2, v3);
                bf16_hl(v0, v1, a0h, a0l);
                bf16_hl(v2, v3, a1h, a1l);
            }
            {   // nt = 2*kcp+1 -> k pair [kcp*16 + 8 + 2*t4]
                int nt = 2 * kcp + 1;
                float2 bpair = *(const float2*)(b1s + nt * 8 + 2 * t4);
                float v0 = fmaxf(c[nt][0] + bpair.x, 0.f);
                float v1 = fmaxf(c[nt][1] + bpair.y, 0.f);
                float v2 = fmaxf(c[nt][2] + bpair.x, 0.f);
                float v3 = fmaxf(c[nt][3] + bpair.y, 0.f);
                if (sA) *(float2*)(g_x1 + (size_t)(nb + gr) * 128 + nt * 8 + 2 * t4) = make_float2(v0, v1);
                if (sB) *(float2*)(g_x1 + (size_t)(nb + gr + 8) * 128 + nt * 8 + 2 * t4) = make_float2(v2, v3);
                bf16_hl(v0, v1, a2h, a2l);
                bf16_hl(v2, v3, a3h, a3l);
            }
            const float4* bq = Bp + kcp * 256 + lane;
            #pragma unroll
            for (int np = 0; np < 8; np++) {
                float4 f = bq[np * 32];
                u32 b0h = __float_as_uint(f.x), b1h = __float_as_uint(f.y);
                u32 b0l = __float_as_uint(f.z), b1l = __float_as_uint(f.w);
                mma_bf16(cp[np], a0h, a1h, a2h, a3h, b0h, b1h);
                mma_bf16(cp[np], a0l, a1l, a2l, a3l, b0h, b1h);
                mma_bf16(cp[np], a0h, a1h, a2h, a3h, b0l, b1l);
            }
        }

        // ---- epilogue: +pb1, LayerNorm(64), softmax / log_softmax ----
        float sumA = 0.f, sqA = 0.f, sumB = 0.f, sqB = 0.f;
        #pragma unroll
        for (int p = 0; p < 8; p++) {
            float2 pb = *(const float2*)(pb1s + p * 8 + 2 * t4);
            cp[p][0] += pb.x; cp[p][1] += pb.y;
            cp[p][2] += pb.x; cp[p][3] += pb.y;
            sumA += cp[p][0] + cp[p][1]; sqA += cp[p][0]*cp[p][0] + cp[p][1]*cp[p][1];
            sumB += cp[p][2] + cp[p][3]; sqB += cp[p][2]*cp[p][2] + cp[p][3]*cp[p][3];
        }
        #pragma unroll
        for (int o = 1; o <= 2; o <<= 1) {
            sumA += __shfl_xor_sync(0xffffffffu, sumA, o);
            sqA  += __shfl_xor_sync(0xffffffffu, sqA, o);
            sumB += __shfl_xor_sync(0xffffffffu, sumB, o);
            sqB  += __shfl_xor_sync(0xffffffffu, sqB, o);
        }
        float muA = sumA * (1.f/64.f), varA = sqA * (1.f/64.f) - muA * muA;
        float muB = sumB * (1.f/64.f), varB = sqB * (1.f/64.f) - muB * muB;
        float invA = rsqrtf(varA + 1e-5f), invB = rsqrtf(varB + 1e-5f);
        float mxA = -1e30f, mxB = -1e30f;
        #pragma unroll
        for (int p = 0; p < 8; p++) {
            float2 gp = *(const float2*)(g1s + p * 8 + 2 * t4);
            float2 bp2 = *(const float2*)(be1s + p * 8 + 2 * t4);
            cp[p][0] = (cp[p][0] - muA) * invA * gp.x + bp2.x;
            cp[p][1] = (cp[p][1] - muA) * invA * gp.y + bp2.y;
            cp[p][2] = (cp[p][2] - muB) * invB * gp.x + bp2.x;
            cp[p][3] = (cp[p][3] - muB) * invB * gp.y + bp2.y;
            mxA = fmaxf(mxA, fmaxf(cp[p][0], cp[p][1]));
            mxB = fmaxf(mxB, fmaxf(cp[p][2], cp[p][3]));
        }
        #pragma unroll
        for (int o = 1; o <= 2; o <<= 1) {
            mxA = fmaxf(mxA, __shfl_xor_sync(0xffffffffu, mxA, o));
            mxB = fmaxf(mxB, __shfl_xor_sync(0xffffffffu, mxB, o));
        }
        float seA = 0.f, seB = 0.f;
        #pragma unroll
        for (int p = 0; p < 8; p++) {
            seA += __expf(cp[p][0] - mxA) + __expf(cp[p][1] - mxA);
            seB += __expf(cp[p][2] - mxB) + __expf(cp[p][3] - mxB);
        }
        #pragma unroll
        for (int o = 1; o <= 2; o <<= 1) {
            seA += __shfl_xor_sync(0xffffffffu, seA, o);
            seB += __shfl_xor_sync(0xffffffffu, seB, o);
        }
        float lseA = __logf(seA), lseB = __logf(seB);
        float rA = 1.f / seA, rB = 1.f / seB;
        #pragma unroll
        for (int p = 0; p < 8; p++) {
            int colo = p * 8 + 2 * t4;
            if (sA) {
                *(float2*)(out + 4 + (size_t)(nb + gr) * 64 + colo) =
                    make_float2(cp[p][0] - mxA - lseA, cp[p][1] - mxA - lseA);
                *(float2*)(g_s + (size_t)(nb + gr) * 64 + colo) =
                    make_float2(__expf(cp[p][0] - mxA) * rA, __expf(cp[p][1] - mxA) * rA);
            }
            if (sB) {
                *(float2*)(out + 4 + (size_t)(nb + gr + 8) * 64 + colo) =
                    make_float2(cp[p][2] - mxB - lseB, cp[p][3] - mxB - lseB);
                *(float2*)(g_s + (size_t)(nb + gr + 8) * 64 + colo) =
                    make_float2(__expf(cp[p][2] - mxB) * rB, __expf(cp[p][3] - mxB) * rB);
            }
        }
    }
}

// ---------------- K_pool_xs: s^T @ [x1 | s] (64x192) + mincut denominator -------
__global__ void k_pool_xs() {
    __shared__ __align__(16) float vv[2][4][192];
    __shared__ float redsh[256];
    int t = threadIdx.x;
    int rg = t >> 4, cg = t & 15;
    int per = (NN + NBP - 1) / NBP;
    int n0 = blockIdx.x * per;
    int n1 = min(n0 + per, NN);

    const float* src;
    int stride;
    if (t < 128)      { src = g_x1 + t;         stride = 128; }
    else if (t < 192) { src = g_s + (t - 128);  stride = 64; }
    else              { src = g_s + (t - 192);  stride = 64; }

    u64 acc[4][6];
    #pragma unroll
    for (int i = 0; i < 4; i++)
        #pragma unroll
        for (int j = 0; j < 6; j++) acc[i][j] = 0ULL;
    float denp = 0.f;

    float r[4], dg[4];
    #pragma unroll
    for (int j = 0; j < 4; j++) {
        int n = n0 + j;
        r[j]  = (n < n1) ? src[(size_t)n * stride] : 0.f;
        dg[j] = (t >= 192 && n < n1) ? __ldg(g_deg + n) : 0.f;
    }
    int pi = 0;
    for (int g = n0; g < n1; g += 4) {
        if (t < 192) {
            #pragma unroll
            for (int j = 0; j < 4; j++) vv[pi][j][t] = r[j];
        } else {
            #pragma unroll
            for (int j = 0; j < 4; j++) denp += dg[j] * r[j] * r[j];
        }
        float rn[4], dn[4];
        #pragma unroll
        for (int j = 0; j < 4; j++) {
            int n = g + 4 + j;
            rn[j] = (n < n1) ? src[(size_t)n * stride] : 0.f;
            dn[j] = (t >= 192 && n < n1) ? __ldg(g_deg + n) : 0.f;
        }
        __syncthreads();
        #pragma unroll
        for (int j = 0; j < 4; j++) {
            float4 s4 = *(const float4*)&vv[pi][j][128 + rg * 4];
            u64 s0 = pack2(s4.x, s4.x), s1 = pack2(s4.y, s4.y);
            u64 s2 = pack2(s4.z, s4.z), s3 = pack2(s4.w, s4.w);
            const ulonglong2* vp = (const ulonglong2*)&vv[pi][j][cg * 12];
            #pragma unroll
            for (int h = 0; h < 3; h++) {
                ulonglong2 b2v = vp[h];
                fma2(acc[0][2*h], s0, b2v.x); fma2(acc[0][2*h+1], s0, b2v.y);
                fma2(acc[1][2*h], s1, b2v.x); fma2(acc[1][2*h+1], s1, b2v.y);
                fma2(acc[2][2*h], s2, b2v.x); fma2(acc[2][2*h+1], s2, b2v.y);
                fma2(acc[3][2*h], s3, b2v.x); fma2(acc[3][2*h+1], s3, b2v.y);
            }
        }
        pi ^= 1;
        #pragma unroll
        for (int j = 0; j < 4; j++) { r[j] = rn[j]; dg[j] = dn[j]; }
    }
    float* base = g_part_xs + (size_t)blockIdx.x * PXS_STRIDE;
    #pragma unroll
    for (int i = 0; i < 4; i++)
        #pragma unroll
        for (int j = 0; j < 6; j++) {
            float f0, f1;
            unpack2(f0, f1, acc[i][j]);
            ((float2*)(base + (rg * 4 + i) * 192 + cg * 12))[j] = make_float2(f0, f1);
        }
    redsh[t] = denp; __syncthreads();
    for (int o = 128; o; o >>= 1) { if (t < o) redsh[t] += redsh[t + o]; __syncthreads(); }
    if (t == 0) base[PXS_DEN] = redsh[0];
}

// ---------------- K_pool_as: s^T @ A_s (64x64) ----------------
__global__ void k_pool_as() {
    __shared__ __align__(16) float sAs[2][4][64];
    __shared__ __align__(16) float sS[2][4][64];
    int t = threadIdx.x;
    int rg = t >> 4, cg = t & 15;
    int j0 = t >> 6, u = t & 63;
    int per = (NN + NBP - 1) / NBP;
    int n0 = blockIdx.x * per;
    int n1 = min(n0 + per, NN);

    u64 acc[4][2];
    #pragma unroll
    for (int i = 0; i < 4; i++) { acc[i][0] = 0ULL; acc[i][1] = 0ULL; }

    float ra, rs;
    {
        int n = n0 + j0;
        ra = (n < n1) ? g_As[(size_t)n * 64 + u] : 0.f;
        rs = (n < n1) ? g_s[(size_t)n * 64 + u]  : 0.f;
    }
    int pi = 0;
    for (int g = n0; g < n1; g += 4) {
        sAs[pi][j0][u] = ra;
        sS[pi][j0][u]  = rs;
        float ran, rsn;
        {
            int n = g + 4 + j0;
            ran = (n < n1) ? g_As[(size_t)n * 64 + u] : 0.f;
            rsn = (n < n1) ? g_s[(size_t)n * 64 + u]  : 0.f;
        }
        __syncthreads();
        #pragma unroll
        for (int j = 0; j < 4; j++) {
            float4 s4 = *(const float4*)&sS[pi][j][rg * 4];
            u64 s0 = pack2(s4.x, s4.x), s1 = pack2(s4.y, s4.y);
            u64 s2 = pack2(s4.z, s4.z), s3 = pack2(s4.w, s4.w);
            ulonglong2 b2v = *(const ulonglong2*)&sAs[pi][j][cg * 4];
            fma2(acc[0][0], s0, b2v.x); fma2(acc[0][1], s0, b2v.y);
            fma2(acc[1][0], s1, b2v.x); fma2(acc[1][1], s1, b2v.y);
            fma2(acc[2][0], s2, b2v.x); fma2(acc[2][1], s2, b2v.y);
            fma2(acc[3][0], s3, b2v.x); fma2(acc[3][1], s3, b2v.y);
        }
        pi ^= 1;
        ra = ran; rs = rsn;
    }
    float* base = g_part_as + (size_t)blockIdx.x * PAS_STRIDE;
    #pragma unroll
    for (int i = 0; i < 4; i++) {
        float f0, f1;
        unpack2(f0, f1, acc[i][0]);
        ((float2*)(base + (rg * 4 + i) * 64 + cg * 4))[0] = make_float2(f0, f1);
        unpack2(f0, f1, acc[i][1]);
        ((float2*)(base + (rg * 4 + i) * 64 + cg * 4))[1] = make_float2(f0, f1);
    }
}

// ---------------- K_reduce ----------------
__global__ void k_reduce() {
    int i = blockIdx.x * blockDim.x + threadIdx.x;
    if (i >= RED_SIZE) return;
    float s = 0.f;
    if (i == 16384) {
        for (int b = 0; b < NBP; b++) s += g_part_xs[(size_t)b * PXS_STRIDE + PXS_DEN];
    } else {
        int a = i >> 8, c = i & 255;
        if (c < 128) {
            int off = a * 192 + c;
            for (int b = 0; b < NBP; b++) s += g_part_xs[(size_t)b * PXS_STRIDE + off];
        } else if (c < 192) {
            int off = a * 64 + (c - 128);
            for (int b = 0; b < NBP; b++) s += g_part_as[(size_t)b * PAS_STRIDE + off];
        } else {
            int off = a * 192 + 128 + (c - 192);
            for (int b = 0; b < NBP; b++) s += g_part_xs[(size_t)b * PXS_STRIDE + off];
        }
    }
    g_red[i] = s;
}

// ---------------- K4m: mc1, o1, pruning -> M ----------------
__global__ void k_small1(float* __restrict__ out) {
    __shared__ float sadj[64 * 65];
    __shared__ float ssts[64 * 65];
    __shared__ float red[256];
    __shared__ float dsi[64];
    int t = threadIdx.x;
    for (int i = t; i < 4096; i += 256) {
        int c = i >> 6, j = i & 63;
        sadj[c * 65 + j] = g_red[c * 256 + 128 + j];
        ssts[c * 65 + j] = g_red[c * 256 + 192 + j];
    }
    __syncthreads();
    float p = 0.f;
    #pragma unroll 4
    for (int i = t; i < 4096; i += 256) {
        float v = ssts[(i >> 6) * 65 + (i & 63)];
        p += v * v;
    }
    red[t] = p; __syncthreads();
    for (int o = 128; o; o >>= 1) { if (t < o) red[t] += red[t + o]; __syncthreads(); }
    float nrm = sqrtf(red[0]); __syncthreads();
    float q = 0.f;
    #pragma unroll 4
    for (int i = t; i < 4096; i += 256) {
        int c = i >> 6, j = i & 63;
        float v = ssts[c * 65 + j] / (nrm + 1e-10f) - ((c == j) ? 0.125f : 0.f);
        q += v * v;
    }
    red[t] = q; __syncthreads();
    for (int o = 128; o; o >>= 1) { if (t < o) red[t] += red[t + o]; __syncthreads(); }
    float o1 = sqrtf(red[0]); __syncthreads();
    float tp = (t < 64) ? sadj[t * 65 + t] : 0.f;
    red[t] = tp; __syncthreads();
    for (int o = 128; o; o >>= 1) { if (t < o) red[t] += red[t + o]; __syncthreads(); }
    if (t == 0) {
        float den = g_red[16384];
        out[0] = -red[0] / (den + 1e-10f);
        out[1] = o1;
    }
    __syncthreads();
    if (t < 64) {
        float rs = 0.f;
        #pragma unroll
        for (int j = 0; j < 64; j++) if (j != t) rs += sadj[t * 65 + j];
        dsi[t] = 1.f / (sqrtf(rs) + 1e-15f);
    }
    __syncthreads();
    for (int i = t; i < 4096; i += 256) {
        int c = i >> 6, j = i & 63;
        float a = (c == j) ? 0.f : (sadj[c * 65 + j] * dsi[c] * dsi[j]);
        g_M[i] = (a > (1.0f / 63.0f)) ? 1.f : 0.f;
    }
}

// ---------------- K4a: pooled GraphConv + LN + softmax ----------------
#define L2_SMEM_FLOATS (16512*2 + 2048 + 128*4 + 16*2 + 64)

__global__ void k_layer2(const float* __restrict__ W2rel, const float* __restrict__ b2,
                         const float* __restrict__ W2root,
                         const float* __restrict__ pW2, const float* __restrict__ pb2,
                         const float* __restrict__ g2, const float* __restrict__ be2,
                         float* __restrict__ out) {
    extern __shared__ float sm2[];
    float* w2a  = sm2;
    float* w2b  = w2a + 16512;
    float* pws  = w2b + 16512;
    float* ag   = pws + 2048;
    float* pr   = ag + 128;
    float* x2r  = pr + 128;
    float* praw = x2r + 128;
    float* r16  = praw + 128;
    float* v16  = r16 + 16;
    float* Mcol = v16 + 16;
    int c = blockIdx.x;
    int t = threadIdx.x;

    for (int i = t; i < 16384; i += 128) {
        int o = i >> 7, k = i & 127;
        w2a[k * 129 + o] = W2rel[i];
        w2b[k * 129 + o] = W2root[i];
    }
    for (int i = t; i < 2048; i += 128) pws[i] = pW2[i];
    if (t < 64) Mcol[t] = g_M[t * 64 + c];
    pr[t] = g_red[c * 256 + t];
    __syncthreads();

    float a = 0.f;
    #pragma unroll 16
    for (int cp = 0; cp < 64; cp++) a += Mcol[cp] * g_red[cp * 256 + t];
    ag[t] = a;
    __syncthreads();

    float acc = __ldg(b2 + t);
    #pragma unroll 8
    for (int k = 0; k < 128; k++)
        acc += ag[k] * w2a[k * 129 + t] + pr[k] * w2b[k * 129 + t];
    acc = fmaxf(acc, 0.f);
    x2r[t] = acc;
    __syncthreads();
    {
        int j2 = t >> 3, seg = t & 7;
        float p = 0.f;
        #pragma unroll
        for (int k = seg; k < 128; k += 8) p += x2r[k] * pws[j2 * 128 + k];
        praw[t] = p;
    }
    __syncthreads();
    if (t < 16) {
        float raw = pb2[t];
        #pragma unroll
        for (int s = 0; s < 8; s++) raw += praw[t * 8 + s];
        r16[t] = raw;
    }
    __syncthreads();
    if (t < 16) {
        float mu = 0.f, sq = 0.f;
        #pragma unroll
        for (int j = 0; j < 16; j++) { mu += r16[j]; sq += r16[j] * r16[j]; }
        mu *= (1.f / 16.f);
        float var = sq * (1.f / 16.f) - mu * mu;
        v16[t] = (r16[t] - mu) * rsqrtf(var + 1e-5f) * g2[t] + be2[t];
    }
    __syncthreads();
    if (t < 16) {
        float mx = -1e30f;
        #pragma unroll
        for (int j = 0; j < 16; j++) mx = fmaxf(mx, v16[j]);
        float se = 0.f;
        #pragma unroll
        for (int j = 0; j < 16; j++) se += __expf(v16[j] - mx);
        float e = __expf(v16[t] - mx);
        out[4 + NN * 64 + c * 16 + t] = v16[t] - mx - __logf(se);
        g_s2[c * 16 + t] = e / se;
    }
}

// ---------------- K4b: dense mincut -> mc2, o2 ----------------
__global__ void k_small2(float* __restrict__ out) {
    __shared__ float sM[64 * 65];
    __shared__ float s2s[NC1 * NC2];
    __shared__ float As2[NC1 * NC2];
    __shared__ float padj[NC2 * NC2];
    __shared__ float sTs[NC2 * NC2];
    __shared__ float red[256];
    int t = threadIdx.x;
    for (int i = t; i < 4096; i += 256) sM[(i >> 6) * 65 + (i & 63)] = g_M[i];
    for (int i = t; i < 1024; i += 256) s2s[i] = g_s2[i];
    __syncthreads();
    for (int i = t; i < 1024; i += 256) {
        int c = i >> 4, j = i & 15;
        float a = 0.f;
        #pragma unroll 16
        for (int cp = 0; cp < 64; cp++) a += sM[c * 65 + cp] * s2s[cp * 16 + j];
        As2[i] = a;
    }
    __syncthreads();
    {
        int aI = t >> 4, bI = t & 15;
        float pa = 0.f, st = 0.f;
        #pragma unroll 16
        for (int c = 0; c < 64; c++) {
            float sa = s2s[c * 16 + aI];
            pa += sa * As2[c * 16 + bI];
            st += sa * s2s[c * 16 + bI];
        }
        padj[t] = pa; sTs[t] = st;
    }
    __syncthreads();
    float dp = 0.f;
    if (t < 64) {
        float d = 0.f;
        #pragma unroll
        for (int j = 0; j < 64; j++) d += sM[t * 65 + j];
        float accv = 0.f;
        #pragma unroll
        for (int j = 0; j < 16; j++) { float s = s2s[t * 16 + j]; accv += s * s; }
        dp = d * accv;
    }
    red[t] = dp; __syncthreads();
    for (int o = 128; o; o >>= 1) { if (t < o) red[t] += red[t + o]; __syncthreads(); }
    float den2 = red[0]; __syncthreads();
    float trp = (t < 16) ? padj[t * 16 + t] : 0.f;
    red[t] = trp; __syncthreads();
    for (int o = 128; o; o >>= 1) { if (t < o) red[t] += red[t + o]; __syncthreads(); }
    float tr2 = red[0]; __syncthreads();
    float np = sTs[t] * sTs[t];
    red[t] = np; __syncthreads();
    for (int o = 128; o; o >>= 1) { if (t < o) red[t] += red[t + o]; __syncthreads(); }
    float norm2 = sqrtf(red[0]); __syncthreads();
    float diff = sTs[t] / (norm2 + 1e-10f) - (((t >> 4) == (t & 15)) ? 0.25f : 0.f);
    red[t] = diff * diff; __syncthreads();
    for (int o = 128; o; o >>= 1) { if (t < o) red[t] += red[t + o]; __syncthreads(); }
    if (t == 0) {
        out[2] = -tr2 / (den2 + 1e-10f);
        out[3] = sqrtf(red[0]);
    }
}

// ---------------- launch ----------------
extern "C" void kernel_launch(void* const* d_in, const int* in_sizes, int n_in,
                              void* d_out, int out_size) {
    const float* x     = (const float*)d_in[0];
    const int*   ei    = (const int*)d_in[1];
    const float* mask  = (const float*)d_in[2];
    const float* W1rel = (const float*)d_in[3];
    const float* b1    = (const float*)d_in[4];
    const float* W1rt  = (const float*)d_in[5];
    const float* pW1   = (const float*)d_in[6];
    const float* pb1   = (const float*)d_in[7];
    const float* g1    = (const float*)d_in[8];
    const float* be1   = (const float*)d_in[9];
    const float* W2rel = (const float*)d_in[10];
    const float* b2    = (const float*)d_in[11];
    const float* W2rt  = (const float*)d_in[12];
    const float* pW2   = (const float*)d_in[13];
    const float* pb2   = (const float*)d_in[14];
    const float* g2    = (const float*)d_in[15];
    const float* be2   = (const float*)d_in[16];
    float* out = (float*)d_out;
    const int* row = ei;
    const int* col = ei + EE;

    cudaFuncSetAttribute(k_node, cudaFuncAttributeMaxDynamicSharedMemorySize,
                         K2_SMEM_BYTES);
    cudaFuncSetAttribute(k_layer2, cudaFuncAttributeMaxDynamicSharedMemorySize,
                         L2_SMEM_FLOATS * (int)sizeof(float));

    k_zero<<<(NN * INC / 4 + 255) / 256, 256>>>();
    k_scatter_agg<<<(EE * 16) / 256, 256>>>(x, row, col, mask);
    k_node<<<148, K2_THREADS, K2_SMEM_BYTES>>>(
        x, mask, W1rel, b1, W1rt, pW1, pb1, g1, be1, out);
    k_scatter_As<<<(EE * 16) / 256, 256>>>(row, col);
    k_pool_xs<<<NBP, 256>>>();
    k_pool_as<<<NBP, 256>>>();
    k_reduce<<<(RED_SIZE + 255) / 256, 256>>>();
    k_small1<<<1, 256>>>(out);
    k_layer2<<<64, 128, L2_SMEM_FLOATS * sizeof(float)>>>(W2rel, b2, W2rt, pW2, pb2, g2, be2, out);
    k_small2<<<1, 256>>>(out);
}